// round 1
// baseline (speedup 1.0000x reference)
#include <cuda_runtime.h>
#include <cuda_bf16.h>

// Problem constants
#define NROWS 8192          // n = 2*B
#define BROWS 4096          // B
#define DDIM  256           // feature dim
#define BLK   128           // tile edge (pairs)
#define KC    16            // k-chunk
#define NT    64            // NROWS/BLK tiles per dim
#define NTRI  (NT*(NT+1)/2) // 2080 upper-triangular tiles

// Device scratch (no allocations allowed)
__device__ float  g_sq[NROWS];
__device__ double g_colsum[DDIM];
__device__ double g_S1;
__device__ double g_result;
__device__ float  g_scale;     // 1/(16*bandwidth)

// ---------------------------------------------------------------------------
// Zero the accumulators that prep() atomically adds into.
__global__ void zero_kernel() {
    int t = blockIdx.x * blockDim.x + threadIdx.x;
    if (t < DDIM) g_colsum[t] = 0.0;
    if (t == 0)   g_S1 = 0.0;
}

// ---------------------------------------------------------------------------
// Per-row squared norms + column sums + total sum of squares.
// grid = 256 blocks, 256 threads; block b handles rows [b*32, b*32+32)
__global__ void prep_kernel(const float* __restrict__ src,
                            const float* __restrict__ tgt) {
    __shared__ float red[DDIM];
    int t = threadIdx.x;
    int b = blockIdx.x;
    double csum = 0.0;
    double s1   = 0.0;
    for (int rr = 0; rr < 32; rr++) {
        int r = b * 32 + rr;
        const float* row = (r < BROWS) ? (src + (size_t)r * DDIM)
                                       : (tgt + (size_t)(r - BROWS) * DDIM);
        float v = row[t];
        csum += (double)v;
        red[t] = v * v;
        __syncthreads();
        #pragma unroll
        for (int s = 128; s > 0; s >>= 1) {
            if (t < s) red[t] += red[t + s];
            __syncthreads();
        }
        if (t == 0) {
            g_sq[r] = red[0];
            s1 += (double)red[0];
        }
        __syncthreads();
    }
    atomicAdd(&g_colsum[t], csum);
    if (t == 0) atomicAdd(&g_S1, s1);
}

// ---------------------------------------------------------------------------
// Bandwidth: sum_l2 = 2n*S1 - 2*||colsum||^2 ; bw = sum/(n^2-n)/4.
// Also zeroes g_result (runs before pair kernel).
__global__ void bw_kernel() {
    double ss = 0.0;
    for (int d = 0; d < DDIM; d++) {
        double c = g_colsum[d];
        ss += c * c;
    }
    const double n = (double)NROWS;
    double sum_l2 = 2.0 * n * g_S1 - 2.0 * ss;
    double bw = sum_l2 / (n * n - n) / 4.0;   // / KERNEL_MUL^(KERNEL_NUM/2)
    g_scale = (float)(1.0 / (bw * 16.0));     // largest sigma = bw*2^4
    g_result = 0.0;
}

// ---------------------------------------------------------------------------
// Main pairwise kernel: upper-triangular 128x128 tiles, register-tiled
// 8x8 per thread, fused exp-kernel epilogue, signed double accumulation.
__global__ void __launch_bounds__(256, 2)
pair_kernel(const float* __restrict__ src, const float* __restrict__ tgt) {
    // Decode triangular tile index -> (bi, bj), bj >= bi
    int rem = blockIdx.x;
    int bi = 0;
    while (rem >= NT - bi) { rem -= NT - bi; bi++; }
    int bj = bi + rem;

    const float* Ab = (bi < NT/2) ? src + (size_t)bi * BLK * DDIM
                                  : tgt + (size_t)(bi - NT/2) * BLK * DDIM;
    const float* Bb = (bj < NT/2) ? src + (size_t)bj * BLK * DDIM
                                  : tgt + (size_t)(bj - NT/2) * BLK * DDIM;

    __shared__ float As[KC][BLK + 4];
    __shared__ float Bs[KC][BLK + 4];

    int tid = threadIdx.x;
    int tx = tid & 15;         // 0..15 -> j groups of 8
    int ty = tid >> 4;         // 0..15 -> i groups of 8

    float acc[8][8];
    #pragma unroll
    for (int i = 0; i < 8; i++)
        #pragma unroll
        for (int j = 0; j < 8; j++) acc[i][j] = 0.0f;

    for (int k0 = 0; k0 < DDIM; k0 += KC) {
        // Load 128x16 A-tile and B-tile (512 float4s each; 2 per thread)
        #pragma unroll
        for (int l = 0; l < 2; l++) {
            int f  = tid + l * 256;       // float4 index 0..511
            int r  = f >> 2;
            int kq = (f & 3) * 4;
            float4 va = *(const float4*)(Ab + (size_t)r * DDIM + k0 + kq);
            As[kq + 0][r] = va.x; As[kq + 1][r] = va.y;
            As[kq + 2][r] = va.z; As[kq + 3][r] = va.w;
            float4 vb = *(const float4*)(Bb + (size_t)r * DDIM + k0 + kq);
            Bs[kq + 0][r] = vb.x; Bs[kq + 1][r] = vb.y;
            Bs[kq + 2][r] = vb.z; Bs[kq + 3][r] = vb.w;
        }
        __syncthreads();

        #pragma unroll
        for (int kk = 0; kk < KC; kk++) {
            float a[8], bv[8];
            float4 a0 = *(const float4*)&As[kk][ty * 8];
            float4 a1 = *(const float4*)&As[kk][ty * 8 + 4];
            a[0]=a0.x; a[1]=a0.y; a[2]=a0.z; a[3]=a0.w;
            a[4]=a1.x; a[5]=a1.y; a[6]=a1.z; a[7]=a1.w;
            float4 b0 = *(const float4*)&Bs[kk][tx * 8];
            float4 b1 = *(const float4*)&Bs[kk][tx * 8 + 4];
            bv[0]=b0.x; bv[1]=b0.y; bv[2]=b0.z; bv[3]=b0.w;
            bv[4]=b1.x; bv[5]=b1.y; bv[6]=b1.z; bv[7]=b1.w;
            #pragma unroll
            for (int i = 0; i < 8; i++)
                #pragma unroll
                for (int j = 0; j < 8; j++)
                    acc[i][j] = fmaf(a[i], bv[j], acc[i][j]);
        }
        __syncthreads();
    }

    // Epilogue: l2 -> 5-kernel sum via one exp + 4 squarings
    int i0 = bi * BLK + ty * 8;
    int j0 = bj * BLK + tx * 8;
    float sqi[8], sqj[8];
    #pragma unroll
    for (int i = 0; i < 8; i++) sqi[i] = g_sq[i0 + i];
    #pragma unroll
    for (int j = 0; j < 8; j++) sqj[j] = g_sq[j0 + j];
    float c = g_scale;

    double local = 0.0;
    #pragma unroll
    for (int i = 0; i < 8; i++) {
        #pragma unroll
        for (int j = 0; j < 8; j++) {
            float l2 = fmaxf(sqi[i] + sqj[j] - 2.0f * acc[i][j], 0.0f);
            float e  = __expf(-l2 * c);      // exp(-l2/(16 bw))
            float s  = e;
            float p  = e;
            p *= p; s += p;                  // e^2
            p *= p; s += p;                  // e^4
            p *= p; s += p;                  // e^8
            p *= p; s += p;                  // e^16
            local += (double)s;
        }
    }

    // Tile weight: sign from which halves, x2 for off-diagonal (mirror tile)
    double w = ((bi < NT/2) == (bj < NT/2)) ? 1.0 : -1.0;
    if (bj > bi) w *= 2.0;
    local *= w;

    // Block reduce (double) + single atomic per block
    __shared__ double dred[256];
    dred[tid] = local;
    __syncthreads();
    #pragma unroll
    for (int s = 128; s > 0; s >>= 1) {
        if (tid < s) dred[tid] += dred[tid + s];
        __syncthreads();
    }
    if (tid == 0) atomicAdd(&g_result, dred[0]);
}

// ---------------------------------------------------------------------------
__global__ void finalize_kernel(float* __restrict__ out) {
    out[0] = (float)(g_result * (1.0 / ((double)BROWS * (double)BROWS)));
}

extern "C" void kernel_launch(void* const* d_in, const int* in_sizes, int n_in,
                              void* d_out, int out_size) {
    const float* src = (const float*)d_in[0];
    const float* tgt = (const float*)d_in[1];
    float* out = (float*)d_out;
    (void)in_sizes; (void)n_in; (void)out_size;

    zero_kernel<<<1, 512>>>();
    prep_kernel<<<256, 256>>>(src, tgt);
    bw_kernel<<<1, 1>>>();
    pair_kernel<<<NTRI, 256>>>(src, tgt);
    finalize_kernel<<<1, 1>>>(out);
}

// round 3
// speedup vs baseline: 1.6966x; 1.6966x over previous
#include <cuda_runtime.h>
#include <cuda_bf16.h>
#include <cstdint>

// Problem constants
#define NROWS 8192          // n = 2*B
#define BROWS 4096          // B
#define DDIM  256           // feature dim
#define BLK   128           // tile edge
#define NT    64            // NROWS/BLK
#define NTRI  (NT*(NT+1)/2) // 2080 upper-triangular tiles
#define KC    32            // k columns per outer iteration
#define ROWB  80            // smem row stride bytes (64B data + 16B pad, bank-perfect)

// Device scratch (no allocations allowed)
__device__ float  g_sq[NROWS];
__device__ double g_colsum[DDIM];
__device__ double g_S1;
__device__ double g_result;
__device__ float  g_scale;     // 1/(16*bandwidth)
__device__ __nv_bfloat16 g_hi[NROWS * DDIM];
__device__ __nv_bfloat16 g_lo[NROWS * DDIM];

// ---------------------------------------------------------------------------
__device__ __forceinline__ uint32_t smem_u32(const void* p) {
    uint32_t a;
    asm("{ .reg .u64 t; cvta.to.shared.u64 t, %1; cvt.u32.u64 %0, t; }"
        : "=r"(a) : "l"(p));
    return a;
}

__device__ __forceinline__ void ldsm4(uint32_t* r, uint32_t addr) {
    asm volatile("ldmatrix.sync.aligned.m8n8.x4.shared.b16 {%0,%1,%2,%3}, [%4];"
                 : "=r"(r[0]), "=r"(r[1]), "=r"(r[2]), "=r"(r[3]) : "r"(addr));
}

__device__ __forceinline__ void mma16816(float* c, const uint32_t* a,
                                         uint32_t b0, uint32_t b1) {
    asm volatile(
        "mma.sync.aligned.m16n8k16.row.col.f32.bf16.bf16.f32 "
        "{%0,%1,%2,%3}, {%4,%5,%6,%7}, {%8,%9}, {%0,%1,%2,%3};"
        : "+f"(c[0]), "+f"(c[1]), "+f"(c[2]), "+f"(c[3])
        : "r"(a[0]), "r"(a[1]), "r"(a[2]), "r"(a[3]), "r"(b0), "r"(b1));
}

// ---------------------------------------------------------------------------
__global__ void zero_kernel() {
    int t = blockIdx.x * blockDim.x + threadIdx.x;
    if (t < DDIM) g_colsum[t] = 0.0;
    if (t == 0)   g_S1 = 0.0;
}

// ---------------------------------------------------------------------------
// Per-row squared norms + column sums + total sum of squares + bf16 hi/lo split.
__global__ void prep_kernel(const float* __restrict__ src,
                            const float* __restrict__ tgt) {
    __shared__ float red[DDIM];
    int t = threadIdx.x;
    int b = blockIdx.x;
    double csum = 0.0;
    double s1   = 0.0;
    for (int rr = 0; rr < 32; rr++) {
        int r = b * 32 + rr;
        const float* row = (r < BROWS) ? (src + (size_t)r * DDIM)
                                       : (tgt + (size_t)(r - BROWS) * DDIM);
        float v = row[t];
        // bf16 two-term split: v = hi + lo (lo captures next 8 mantissa bits)
        __nv_bfloat16 h = __float2bfloat16(v);
        float hv = __bfloat162float(h);
        g_hi[(size_t)r * DDIM + t] = h;
        g_lo[(size_t)r * DDIM + t] = __float2bfloat16(v - hv);

        csum += (double)v;
        red[t] = v * v;
        __syncthreads();
        #pragma unroll
        for (int s = 128; s > 0; s >>= 1) {
            if (t < s) red[t] += red[t + s];
            __syncthreads();
        }
        if (t == 0) {
            g_sq[r] = red[0];
            s1 += (double)red[0];
        }
        __syncthreads();
    }
    atomicAdd(&g_colsum[t], csum);
    if (t == 0) atomicAdd(&g_S1, s1);
}

// ---------------------------------------------------------------------------
__global__ void bw_kernel() {
    double ss = 0.0;
    for (int d = 0; d < DDIM; d++) {
        double c = g_colsum[d];
        ss += c * c;
    }
    const double n = (double)NROWS;
    double sum_l2 = 2.0 * n * g_S1 - 2.0 * ss;
    double bw = sum_l2 / (n * n - n) / 4.0;   // / KERNEL_MUL^(KERNEL_NUM/2)
    g_scale = (float)(1.0 / (bw * 16.0));     // largest sigma = bw*2^4
    g_result = 0.0;
}

// ---------------------------------------------------------------------------
// HMMA pair kernel: 128x128 tile per CTA, split-bf16 3-product mma.sync.
// 8 warps: wy in {0,1} (m 2x64), wx in {0..3} (n 4x32).
__global__ void __launch_bounds__(256, 2)
pair3_kernel() {
    __shared__ __align__(16) char sAhi[BLK * ROWB];
    __shared__ __align__(16) char sAlo[BLK * ROWB];
    __shared__ __align__(16) char sBhi[BLK * ROWB];
    __shared__ __align__(16) char sBlo[BLK * ROWB];
    __shared__ float  sqa[BLK];
    __shared__ float  sqb[BLK];
    __shared__ double dred[256];

    int tid  = threadIdx.x;
    int lane = tid & 31;
    int wid  = tid >> 5;
    int wy   = wid >> 2;      // 0..1
    int wx   = wid & 3;       // 0..3

    // Decode triangular tile index -> (bi, bj), bj >= bi
    int rem = blockIdx.x;
    int bi = 0;
    while (rem >= NT - bi) { rem -= NT - bi; bi++; }
    int bj = bi + rem;

    const __nv_bfloat16* Ah = g_hi + (size_t)bi * BLK * DDIM;
    const __nv_bfloat16* Al = g_lo + (size_t)bi * BLK * DDIM;
    const __nv_bfloat16* Bh = g_hi + (size_t)bj * BLK * DDIM;
    const __nv_bfloat16* Bl = g_lo + (size_t)bj * BLK * DDIM;

    if (tid < BLK) {
        sqa[tid] = g_sq[bi * BLK + tid];
        sqb[tid] = g_sq[bj * BLK + tid];
    }

    float acc[4][4][4];
    #pragma unroll
    for (int mt = 0; mt < 4; mt++)
        #pragma unroll
        for (int nt = 0; nt < 4; nt++)
            #pragma unroll
            for (int e = 0; e < 4; e++) acc[mt][nt][e] = 0.0f;

    uint32_t uAhi = smem_u32(sAhi);
    uint32_t uAlo = smem_u32(sAlo);
    uint32_t uBhi = smem_u32(sBhi);
    uint32_t uBlo = smem_u32(sBlo);

    // Per-lane ldmatrix base offsets (bytes) within each matrix
    // A (16x16 frag): row = wy*64 + mt*16 + (lane&15), +16B for k8 group
    uint32_t a_off = (uint32_t)(wy * 64 + (lane & 15)) * ROWB + ((lane >> 4) << 4);
    // B (two n8 frags per x4): nrow = wx*32 + bp*16 + (lane&7) + ((lane>>4)<<3)
    uint32_t b_off = (uint32_t)(wx * 32 + (lane & 7) + ((lane >> 4) << 3)) * ROWB
                   + (((lane >> 3) & 1) << 4);

    for (int c = 0; c < DDIM / KC; c++) {
        int k0 = c * KC;
        // Load 4 matrices: 128 rows x 32 bf16 each; 2 x 16B per thread per matrix
        #pragma unroll
        for (int l = 0; l < 2; l++) {
            int chunk = tid + l * 256;          // 0..511
            int r  = chunk >> 2;
            int c16 = chunk & 3;
            uint32_t sw = (uint32_t)r * ROWB + (uint32_t)c16 * 16;
            size_t go = (size_t)r * DDIM + k0 + c16 * 8;
            *(float4*)(sAhi + sw) = *(const float4*)(Ah + go);
            *(float4*)(sAlo + sw) = *(const float4*)(Al + go);
            *(float4*)(sBhi + sw) = *(const float4*)(Bh + go);
            *(float4*)(sBlo + sw) = *(const float4*)(Bl + go);
        }
        __syncthreads();

        #pragma unroll
        for (int ks = 0; ks < 2; ks++) {
            uint32_t kb = (uint32_t)ks * 32;    // 16 bf16 = 32 bytes

            // B fragments: bp=0 covers nt 0,1 ; bp=1 covers nt 2,3
            uint32_t bhi[2][4], blo[2][4];
            #pragma unroll
            for (int bp = 0; bp < 2; bp++) {
                uint32_t off = b_off + (uint32_t)bp * 16 * ROWB + kb;
                ldsm4(bhi[bp], uBhi + off);
                ldsm4(blo[bp], uBlo + off);
            }

            uint32_t a[4][4];
            // --- A = hi: products hh and hl ---
            #pragma unroll
            for (int mt = 0; mt < 4; mt++)
                ldsm4(a[mt], uAhi + a_off + (uint32_t)mt * 16 * ROWB + kb);
            #pragma unroll
            for (int mt = 0; mt < 4; mt++) {
                #pragma unroll
                for (int nt = 0; nt < 4; nt++) {
                    mma16816(acc[mt][nt], a[mt],
                             bhi[nt >> 1][(nt & 1) * 2], bhi[nt >> 1][(nt & 1) * 2 + 1]);
                    mma16816(acc[mt][nt], a[mt],
                             blo[nt >> 1][(nt & 1) * 2], blo[nt >> 1][(nt & 1) * 2 + 1]);
                }
            }
            // --- A = lo: product lh ---
            #pragma unroll
            for (int mt = 0; mt < 4; mt++)
                ldsm4(a[mt], uAlo + a_off + (uint32_t)mt * 16 * ROWB + kb);
            #pragma unroll
            for (int mt = 0; mt < 4; mt++)
                #pragma unroll
                for (int nt = 0; nt < 4; nt++)
                    mma16816(acc[mt][nt], a[mt],
                             bhi[nt >> 1][(nt & 1) * 2], bhi[nt >> 1][(nt & 1) * 2 + 1]);
        }
        __syncthreads();
    }

    // Epilogue: l2 -> 5-kernel sum via one exp + 4 squarings
    float cscale = g_scale;
    double local = 0.0;
    int r0 = wy * 64 + (lane >> 2);
    int c0 = wx * 32 + 2 * (lane & 3);
    #pragma unroll
    for (int mt = 0; mt < 4; mt++) {
        #pragma unroll
        for (int nt = 0; nt < 4; nt++) {
            #pragma unroll
            for (int e = 0; e < 4; e++) {
                int i = r0 + mt * 16 + ((e >> 1) << 3);
                int j = c0 + nt * 8 + (e & 1);
                float l2 = fmaxf(sqa[i] + sqb[j] - 2.0f * acc[mt][nt][e], 0.0f);
                float ex = __expf(-l2 * cscale);
                float s  = ex;
                float p  = ex;
                p *= p; s += p;   // e^2
                p *= p; s += p;   // e^4
                p *= p; s += p;   // e^8
                p *= p; s += p;   // e^16
                local += (double)s;
            }
        }
    }

    // Tile weight: sign from halves, x2 for off-diagonal (mirror tile)
    double w = ((bi < NT / 2) == (bj < NT / 2)) ? 1.0 : -1.0;
    if (bj > bi) w *= 2.0;
    local *= w;

    dred[tid] = local;
    __syncthreads();
    #pragma unroll
    for (int s = 128; s > 0; s >>= 1) {
        if (tid < s) dred[tid] += dred[tid + s];
        __syncthreads();
    }
    if (tid == 0) atomicAdd(&g_result, dred[0]);
}

// ---------------------------------------------------------------------------
__global__ void finalize_kernel(float* __restrict__ out) {
    out[0] = (float)(g_result * (1.0 / ((double)BROWS * (double)BROWS)));
}

extern "C" void kernel_launch(void* const* d_in, const int* in_sizes, int n_in,
                              void* d_out, int out_size) {
    const float* src = (const float*)d_in[0];
    const float* tgt = (const float*)d_in[1];
    float* out = (float*)d_out;
    (void)in_sizes; (void)n_in; (void)out_size;

    zero_kernel<<<1, 512>>>();
    prep_kernel<<<256, 256>>>(src, tgt);
    bw_kernel<<<1, 1>>>();
    pair3_kernel<<<NTRI, 256>>>();
    finalize_kernel<<<1, 1>>>(out);
}

// round 4
// speedup vs baseline: 2.2574x; 1.3305x over previous
#include <cuda_runtime.h>
#include <cuda_bf16.h>
#include <cstdint>

// Problem constants
#define NROWS 8192          // n = 2*B
#define BROWS 4096          // B
#define DDIM  256           // feature dim
#define BLK   128           // tile edge
#define NT    64            // NROWS/BLK
#define NTRI  (NT*(NT+1)/2) // 2080 upper-triangular tiles
#define KC    32            // k columns per chunk
#define NCH   (DDIM/KC)     // 8 chunks
#define ROWB  80            // smem row stride bytes (64B data + 16B pad)
#define MATB  (BLK*ROWB)    // 10240 B per matrix buffer
#define STAGEB (4*MATB)     // 40960 B per stage (Ahi,Alo,Bhi,Blo)
#define DYN_SMEM (2*STAGEB) // 81920 B

// Device scratch (no allocations allowed)
__device__ float  g_sq[NROWS];
__device__ double g_colsum[DDIM];
__device__ double g_S1;
__device__ double g_result;
__device__ float  g_scale;     // 1/(16*bandwidth)
__device__ __nv_bfloat16 g_hi[NROWS * DDIM];
__device__ __nv_bfloat16 g_lo[NROWS * DDIM];

// ---------------------------------------------------------------------------
__device__ __forceinline__ uint32_t smem_u32(const void* p) {
    uint32_t a;
    asm("{ .reg .u64 t; cvta.to.shared.u64 t, %1; cvt.u32.u64 %0, t; }"
        : "=r"(a) : "l"(p));
    return a;
}

__device__ __forceinline__ void ldsm4(uint32_t* r, uint32_t addr) {
    asm volatile("ldmatrix.sync.aligned.m8n8.x4.shared.b16 {%0,%1,%2,%3}, [%4];"
                 : "=r"(r[0]), "=r"(r[1]), "=r"(r[2]), "=r"(r[3]) : "r"(addr));
}

__device__ __forceinline__ void mma16816(float* c, const uint32_t* a,
                                         uint32_t b0, uint32_t b1) {
    asm volatile(
        "mma.sync.aligned.m16n8k16.row.col.f32.bf16.bf16.f32 "
        "{%0,%1,%2,%3}, {%4,%5,%6,%7}, {%8,%9}, {%0,%1,%2,%3};"
        : "+f"(c[0]), "+f"(c[1]), "+f"(c[2]), "+f"(c[3])
        : "r"(a[0]), "r"(a[1]), "r"(a[2]), "r"(a[3]), "r"(b0), "r"(b1));
}

#define CP_ASYNC16(dst, src) \
    asm volatile("cp.async.cg.shared.global [%0], [%1], 16;" \
                 :: "r"(dst), "l"(src) : "memory")
#define CP_COMMIT() asm volatile("cp.async.commit_group;" ::: "memory")
#define CP_WAIT0()  asm volatile("cp.async.wait_group 0;" ::: "memory")

// ---------------------------------------------------------------------------
__global__ void zero_kernel() {
    int t = blockIdx.x * blockDim.x + threadIdx.x;
    if (t < DDIM) g_colsum[t] = 0.0;
    if (t == 0)   g_S1 = 0.0;
}

// ---------------------------------------------------------------------------
// Warp-per-row prep: row norms (shfl reduce), column sums (smem reduce, one
// atomic per column per block), total sumsq, bf16 hi/lo split.
// grid = 256 blocks x 256 threads; block b handles rows [b*32, b*32+32).
__global__ void prep_kernel(const float* __restrict__ src,
                            const float* __restrict__ tgt) {
    __shared__ double csum_s[8][DDIM];
    int tid  = threadIdx.x;
    int lane = tid & 31;
    int w    = tid >> 5;
    int b    = blockIdx.x;

    double csum[8] = {0, 0, 0, 0, 0, 0, 0, 0};
    double s1 = 0.0;

    #pragma unroll
    for (int i = 0; i < 4; i++) {
        int r = b * 32 + w * 4 + i;
        const float* row = (r < BROWS) ? (src + (size_t)r * DDIM)
                                       : (tgt + (size_t)(r - BROWS) * DDIM);
        float sq = 0.0f;
        #pragma unroll
        for (int k = 0; k < 8; k++) {
            int col = lane + 32 * k;
            float x = row[col];
            sq = fmaf(x, x, sq);
            csum[k] += (double)x;
            __nv_bfloat16 h = __float2bfloat16(x);
            g_hi[(size_t)r * DDIM + col] = h;
            g_lo[(size_t)r * DDIM + col] = __float2bfloat16(x - __bfloat162float(h));
        }
        #pragma unroll
        for (int s = 16; s > 0; s >>= 1) sq += __shfl_xor_sync(0xFFFFFFFFu, sq, s);
        if (lane == 0) { g_sq[r] = sq; s1 += (double)sq; }
    }

    #pragma unroll
    for (int k = 0; k < 8; k++) csum_s[w][lane + 32 * k] = csum[k];
    __syncthreads();
    double t = 0.0;
    #pragma unroll
    for (int w2 = 0; w2 < 8; w2++) t += csum_s[w2][tid];
    atomicAdd(&g_colsum[tid], t);
    if (lane == 0) atomicAdd(&g_S1, s1);
}

// ---------------------------------------------------------------------------
__global__ void bw_kernel() {
    double ss = 0.0;
    for (int d = 0; d < DDIM; d++) {
        double c = g_colsum[d];
        ss += c * c;
    }
    const double n = (double)NROWS;
    double sum_l2 = 2.0 * n * g_S1 - 2.0 * ss;
    double bw = sum_l2 / (n * n - n) / 4.0;   // / KERNEL_MUL^(KERNEL_NUM/2)
    g_scale = (float)(1.0 / (bw * 16.0));     // largest sigma = bw*2^4
    g_result = 0.0;
}

// ---------------------------------------------------------------------------
// Issue 8 cp.async (16B) per thread: one KC-chunk of all 4 matrices.
__device__ __forceinline__ void prefetch_chunk(
    uint32_t sbase, const __nv_bfloat16* Ah, const __nv_bfloat16* Al,
    const __nv_bfloat16* Bh, const __nv_bfloat16* Bl, int k0, int tid) {
    #pragma unroll
    for (int l = 0; l < 2; l++) {
        int f   = tid + l * 256;      // 0..511
        int r   = f >> 2;
        int c16 = f & 3;
        uint32_t so = (uint32_t)r * ROWB + (uint32_t)c16 * 16;
        size_t  go = (size_t)r * DDIM + k0 + c16 * 8;
        CP_ASYNC16(sbase + 0 * MATB + so, (const void*)(Ah + go));
        CP_ASYNC16(sbase + 1 * MATB + so, (const void*)(Al + go));
        CP_ASYNC16(sbase + 2 * MATB + so, (const void*)(Bh + go));
        CP_ASYNC16(sbase + 3 * MATB + so, (const void*)(Bl + go));
    }
}

// ---------------------------------------------------------------------------
// HMMA pair kernel: 128x128 tile per CTA, split-bf16 3-product mma.sync,
// cp.async double-buffered K-chunks.
__global__ void __launch_bounds__(256, 2)
pair4_kernel() {
    extern __shared__ __align__(16) char dyn[];
    __shared__ float  sqa[BLK];
    __shared__ float  sqb[BLK];
    __shared__ double dred[256];

    int tid  = threadIdx.x;
    int lane = tid & 31;
    int wid  = tid >> 5;
    int wy   = wid >> 2;      // 0..1
    int wx   = wid & 3;       // 0..3

    // Decode triangular tile index -> (bi, bj), bj >= bi
    int rem = blockIdx.x;
    int bi = 0;
    while (rem >= NT - bi) { rem -= NT - bi; bi++; }
    int bj = bi + rem;

    const __nv_bfloat16* Ah = g_hi + (size_t)bi * BLK * DDIM;
    const __nv_bfloat16* Al = g_lo + (size_t)bi * BLK * DDIM;
    const __nv_bfloat16* Bh = g_hi + (size_t)bj * BLK * DDIM;
    const __nv_bfloat16* Bl = g_lo + (size_t)bj * BLK * DDIM;

    if (tid < BLK) {
        sqa[tid] = g_sq[bi * BLK + tid];
        sqb[tid] = g_sq[bj * BLK + tid];
    }

    float acc[4][4][4];
    #pragma unroll
    for (int mt = 0; mt < 4; mt++)
        #pragma unroll
        for (int nt = 0; nt < 4; nt++)
            #pragma unroll
            for (int e = 0; e < 4; e++) acc[mt][nt][e] = 0.0f;

    uint32_t dynb = smem_u32(dyn);

    // Per-lane ldmatrix offsets (bytes) within a matrix buffer
    uint32_t a_off = (uint32_t)(wy * 64 + (lane & 15)) * ROWB + ((lane >> 4) << 4);
    uint32_t b_off = (uint32_t)(wx * 32 + (lane & 7) + ((lane >> 4) << 3)) * ROWB
                   + (((lane >> 3) & 1) << 4);

    prefetch_chunk(dynb, Ah, Al, Bh, Bl, 0, tid);
    CP_COMMIT();

    for (int c = 0; c < NCH; c++) {
        CP_WAIT0();
        __syncthreads();
        if (c + 1 < NCH) {
            prefetch_chunk(dynb + ((c + 1) & 1) * STAGEB, Ah, Al, Bh, Bl,
                           (c + 1) * KC, tid);
            CP_COMMIT();
        }

        uint32_t ub   = dynb + (c & 1) * STAGEB;
        uint32_t uAhi = ub;
        uint32_t uAlo = ub + MATB;
        uint32_t uBhi = ub + 2 * MATB;
        uint32_t uBlo = ub + 3 * MATB;

        #pragma unroll
        for (int ks = 0; ks < 2; ks++) {
            uint32_t kb = (uint32_t)ks * 32;    // 16 bf16 = 32 bytes

            uint32_t bhi[2][4], blo[2][4];
            #pragma unroll
            for (int bp = 0; bp < 2; bp++) {
                uint32_t off = b_off + (uint32_t)bp * 16 * ROWB + kb;
                ldsm4(bhi[bp], uBhi + off);
                ldsm4(blo[bp], uBlo + off);
            }

            uint32_t a[4][4];
            // --- A = hi: products hh and hl ---
            #pragma unroll
            for (int mt = 0; mt < 4; mt++)
                ldsm4(a[mt], uAhi + a_off + (uint32_t)mt * 16 * ROWB + kb);
            #pragma unroll
            for (int mt = 0; mt < 4; mt++) {
                #pragma unroll
                for (int nt = 0; nt < 4; nt++) {
                    mma16816(acc[mt][nt], a[mt],
                             bhi[nt >> 1][(nt & 1) * 2], bhi[nt >> 1][(nt & 1) * 2 + 1]);
                    mma16816(acc[mt][nt], a[mt],
                             blo[nt >> 1][(nt & 1) * 2], blo[nt >> 1][(nt & 1) * 2 + 1]);
                }
            }
            // --- A = lo: product lh ---
            #pragma unroll
            for (int mt = 0; mt < 4; mt++)
                ldsm4(a[mt], uAlo + a_off + (uint32_t)mt * 16 * ROWB + kb);
            #pragma unroll
            for (int mt = 0; mt < 4; mt++)
                #pragma unroll
                for (int nt = 0; nt < 4; nt++)
                    mma16816(acc[mt][nt], a[mt],
                             bhi[nt >> 1][(nt & 1) * 2], bhi[nt >> 1][(nt & 1) * 2 + 1]);
        }
    }

    // Epilogue: l2 -> 5-kernel sum via one exp + 4 squarings
    float cscale = g_scale;
    double local = 0.0;
    int r0 = wy * 64 + (lane >> 2);
    int c0 = wx * 32 + 2 * (lane & 3);
    #pragma unroll
    for (int mt = 0; mt < 4; mt++) {
        #pragma unroll
        for (int nt = 0; nt < 4; nt++) {
            #pragma unroll
            for (int e = 0; e < 4; e++) {
                int i = r0 + mt * 16 + ((e >> 1) << 3);
                int j = c0 + nt * 8 + (e & 1);
                float l2 = fmaxf(sqa[i] + sqb[j] - 2.0f * acc[mt][nt][e], 0.0f);
                float ex = __expf(-l2 * cscale);
                float s  = ex;
                float p  = ex;
                p *= p; s += p;   // e^2
                p *= p; s += p;   // e^4
                p *= p; s += p;   // e^8
                p *= p; s += p;   // e^16
                local += (double)s;
            }
        }
    }

    // Tile weight: sign from halves, x2 for off-diagonal (mirror tile)
    double w = ((bi < NT / 2) == (bj < NT / 2)) ? 1.0 : -1.0;
    if (bj > bi) w *= 2.0;
    local *= w;

    dred[tid] = local;
    __syncthreads();
    #pragma unroll
    for (int s = 128; s > 0; s >>= 1) {
        if (tid < s) dred[tid] += dred[tid + s];
        __syncthreads();
    }
    if (tid == 0) atomicAdd(&g_result, dred[0]);
}

// ---------------------------------------------------------------------------
__global__ void finalize_kernel(float* __restrict__ out) {
    out[0] = (float)(g_result * (1.0 / ((double)BROWS * (double)BROWS)));
}

extern "C" void kernel_launch(void* const* d_in, const int* in_sizes, int n_in,
                              void* d_out, int out_size) {
    const float* src = (const float*)d_in[0];
    const float* tgt = (const float*)d_in[1];
    float* out = (float*)d_out;
    (void)in_sizes; (void)n_in; (void)out_size;

    cudaFuncSetAttribute(pair4_kernel,
                         cudaFuncAttributeMaxDynamicSharedMemorySize, DYN_SMEM);

    zero_kernel<<<1, 512>>>();
    prep_kernel<<<256, 256>>>(src, tgt);
    bw_kernel<<<1, 1>>>();
    pair4_kernel<<<NTRI, 256, DYN_SMEM>>>();
    finalize_kernel<<<1, 1>>>(out);
}

// round 5
// speedup vs baseline: 2.6732x; 1.1842x over previous
#include <cuda_runtime.h>
#include <cuda_bf16.h>
#include <cstdint>

// Problem constants
#define NROWS 8192          // n = 2*B
#define BROWS 4096          // B
#define DDIM  256           // feature dim
#define BLK   128           // tile edge
#define NT    64            // NROWS/BLK
#define NTRI  (NT*(NT+1)/2) // 2080 upper-triangular tiles
#define KC    32            // k columns per chunk
#define NCH   (DDIM/KC)     // 8 chunks
#define ROWB  80            // smem row stride bytes (64B data + 16B pad)
#define MATB  (BLK*ROWB)    // 10240 B per matrix buffer
#define STAGEB (4*MATB)     // 40960 B per stage (Ahi,Alo,Bhi,Blo)
#define DYN_SMEM (2*STAGEB) // 81920 B

// Device scratch (no allocations allowed)
__device__ float  g_sq[NROWS];
__device__ double g_colsum[DDIM];
__device__ double g_S1;
__device__ double g_result;
__device__ float  g_scale;     // 1/(16*bandwidth)
__device__ __nv_bfloat16 g_hi[NROWS * DDIM];
__device__ __nv_bfloat16 g_lo[NROWS * DDIM];

// ---------------------------------------------------------------------------
__device__ __forceinline__ uint32_t smem_u32(const void* p) {
    uint32_t a;
    asm("{ .reg .u64 t; cvta.to.shared.u64 t, %1; cvt.u32.u64 %0, t; }"
        : "=r"(a) : "l"(p));
    return a;
}

__device__ __forceinline__ void ldsm4(uint32_t* r, uint32_t addr) {
    asm volatile("ldmatrix.sync.aligned.m8n8.x4.shared.b16 {%0,%1,%2,%3}, [%4];"
                 : "=r"(r[0]), "=r"(r[1]), "=r"(r[2]), "=r"(r[3]) : "r"(addr));
}

__device__ __forceinline__ void mma16816(float* c, const uint32_t* a,
                                         uint32_t b0, uint32_t b1) {
    asm volatile(
        "mma.sync.aligned.m16n8k16.row.col.f32.bf16.bf16.f32 "
        "{%0,%1,%2,%3}, {%4,%5,%6,%7}, {%8,%9}, {%0,%1,%2,%3};"
        : "+f"(c[0]), "+f"(c[1]), "+f"(c[2]), "+f"(c[3])
        : "r"(a[0]), "r"(a[1]), "r"(a[2]), "r"(a[3]), "r"(b0), "r"(b1));
}

#define CP_ASYNC16(dst, src) \
    asm volatile("cp.async.cg.shared.global [%0], [%1], 16;" \
                 :: "r"(dst), "l"(src) : "memory")
#define CP_COMMIT() asm volatile("cp.async.commit_group;" ::: "memory")
#define CP_WAIT0()  asm volatile("cp.async.wait_group 0;" ::: "memory")

// ---------------------------------------------------------------------------
__global__ void zero_kernel() {
    int t = blockIdx.x * blockDim.x + threadIdx.x;
    if (t < DDIM) g_colsum[t] = 0.0;
    if (t == 0)   g_S1 = 0.0;
}

// ---------------------------------------------------------------------------
// Warp-per-row prep: row norms (shfl reduce), column sums (smem reduce, one
// atomic per column per block), total sumsq, bf16 hi/lo split.
__global__ void prep_kernel(const float* __restrict__ src,
                            const float* __restrict__ tgt) {
    __shared__ double csum_s[8][DDIM];
    int tid  = threadIdx.x;
    int lane = tid & 31;
    int w    = tid >> 5;
    int b    = blockIdx.x;

    double csum[8] = {0, 0, 0, 0, 0, 0, 0, 0};
    double s1 = 0.0;

    #pragma unroll
    for (int i = 0; i < 4; i++) {
        int r = b * 32 + w * 4 + i;
        const float* row = (r < BROWS) ? (src + (size_t)r * DDIM)
                                       : (tgt + (size_t)(r - BROWS) * DDIM);
        float sq = 0.0f;
        #pragma unroll
        for (int k = 0; k < 8; k++) {
            int col = lane + 32 * k;
            float x = row[col];
            sq = fmaf(x, x, sq);
            csum[k] += (double)x;
            __nv_bfloat16 h = __float2bfloat16(x);
            g_hi[(size_t)r * DDIM + col] = h;
            g_lo[(size_t)r * DDIM + col] = __float2bfloat16(x - __bfloat162float(h));
        }
        #pragma unroll
        for (int s = 16; s > 0; s >>= 1) sq += __shfl_xor_sync(0xFFFFFFFFu, sq, s);
        if (lane == 0) { g_sq[r] = sq; s1 += (double)sq; }
    }

    #pragma unroll
    for (int k = 0; k < 8; k++) csum_s[w][lane + 32 * k] = csum[k];
    __syncthreads();
    double t = 0.0;
    #pragma unroll
    for (int w2 = 0; w2 < 8; w2++) t += csum_s[w2][tid];
    atomicAdd(&g_colsum[tid], t);
    if (lane == 0) atomicAdd(&g_S1, s1);
}

// ---------------------------------------------------------------------------
__global__ void bw_kernel() {
    double ss = 0.0;
    for (int d = 0; d < DDIM; d++) {
        double c = g_colsum[d];
        ss += c * c;
    }
    const double n = (double)NROWS;
    double sum_l2 = 2.0 * n * g_S1 - 2.0 * ss;
    double bw = sum_l2 / (n * n - n) / 4.0;   // / KERNEL_MUL^(KERNEL_NUM/2)
    g_scale = (float)(1.0 / (bw * 16.0));     // largest sigma = bw*2^4
    g_result = 0.0;
}

// ---------------------------------------------------------------------------
// Issue 8 cp.async (16B) per thread: one KC-chunk of all 4 matrices.
__device__ __forceinline__ void prefetch_chunk(
    uint32_t sbase, const __nv_bfloat16* Ah, const __nv_bfloat16* Al,
    const __nv_bfloat16* Bh, const __nv_bfloat16* Bl, int k0, int tid) {
    #pragma unroll
    for (int l = 0; l < 2; l++) {
        int f   = tid + l * 256;      // 0..511
        int r   = f >> 2;
        int c16 = f & 3;
        uint32_t so = (uint32_t)r * ROWB + (uint32_t)c16 * 16;
        size_t  go = (size_t)r * DDIM + k0 + c16 * 8;
        CP_ASYNC16(sbase + 0 * MATB + so, (const void*)(Ah + go));
        CP_ASYNC16(sbase + 1 * MATB + so, (const void*)(Al + go));
        CP_ASYNC16(sbase + 2 * MATB + so, (const void*)(Bh + go));
        CP_ASYNC16(sbase + 3 * MATB + so, (const void*)(Bl + go));
    }
}

// ---------------------------------------------------------------------------
// HMMA pair kernel: 128x128 tile per CTA, split-bf16 3-product mma.sync,
// cp.async double-buffered K-chunks, de-interleaved MMA passes.
__global__ void __launch_bounds__(256, 2)
pair5_kernel() {
    extern __shared__ __align__(16) char dyn[];
    __shared__ float  sqa[BLK];
    __shared__ float  sqb[BLK];
    __shared__ double dred[256];

    int tid  = threadIdx.x;
    int lane = tid & 31;
    int wid  = tid >> 5;
    int wy   = wid >> 2;      // 0..1
    int wx   = wid & 3;       // 0..3

    // Decode triangular tile index -> (bi, bj), bj >= bi
    int rem = blockIdx.x;
    int bi = 0;
    while (rem >= NT - bi) { rem -= NT - bi; bi++; }
    int bj = bi + rem;

    const __nv_bfloat16* Ah = g_hi + (size_t)bi * BLK * DDIM;
    const __nv_bfloat16* Al = g_lo + (size_t)bi * BLK * DDIM;
    const __nv_bfloat16* Bh = g_hi + (size_t)bj * BLK * DDIM;
    const __nv_bfloat16* Bl = g_lo + (size_t)bj * BLK * DDIM;

    if (tid < BLK) {
        sqa[tid] = g_sq[bi * BLK + tid];
        sqb[tid] = g_sq[bj * BLK + tid];
    }

    float acc[4][4][4];
    #pragma unroll
    for (int mt = 0; mt < 4; mt++)
        #pragma unroll
        for (int nt = 0; nt < 4; nt++)
            #pragma unroll
            for (int e = 0; e < 4; e++) acc[mt][nt][e] = 0.0f;

    uint32_t dynb = smem_u32(dyn);

    // Per-lane ldmatrix offsets (bytes) within a matrix buffer
    uint32_t a_off = (uint32_t)(wy * 64 + (lane & 15)) * ROWB + ((lane >> 4) << 4);
    uint32_t b_off = (uint32_t)(wx * 32 + (lane & 7) + ((lane >> 4) << 3)) * ROWB
                   + (((lane >> 3) & 1) << 4);

    prefetch_chunk(dynb, Ah, Al, Bh, Bl, 0, tid);
    CP_COMMIT();

    for (int c = 0; c < NCH; c++) {
        CP_WAIT0();
        __syncthreads();
        if (c + 1 < NCH) {
            prefetch_chunk(dynb + ((c + 1) & 1) * STAGEB, Ah, Al, Bh, Bl,
                           (c + 1) * KC, tid);
            CP_COMMIT();
        }

        uint32_t ub   = dynb + (c & 1) * STAGEB;
        uint32_t uAhi = ub;
        uint32_t uAlo = ub + MATB;
        uint32_t uBhi = ub + 2 * MATB;
        uint32_t uBlo = ub + 3 * MATB;

        #pragma unroll
        for (int ks = 0; ks < 2; ks++) {
            uint32_t kb = (uint32_t)ks * 32;    // 16 bf16 = 32 bytes

            uint32_t bhi[2][4], blo[2][4];
            #pragma unroll
            for (int bp = 0; bp < 2; bp++) {
                uint32_t off = b_off + (uint32_t)bp * 16 * ROWB + kb;
                ldsm4(bhi[bp], uBhi + off);
                ldsm4(blo[bp], uBlo + off);
            }

            uint32_t a[4][4];
            #pragma unroll
            for (int mt = 0; mt < 4; mt++)
                ldsm4(a[mt], uAhi + a_off + (uint32_t)mt * 16 * ROWB + kb);

            // Pass 1: hh — 16 independent MMAs
            #pragma unroll
            for (int mt = 0; mt < 4; mt++)
                #pragma unroll
                for (int nt = 0; nt < 4; nt++)
                    mma16816(acc[mt][nt], a[mt],
                             bhi[nt >> 1][(nt & 1) * 2], bhi[nt >> 1][(nt & 1) * 2 + 1]);

            // Pass 2: hl — 16 independent MMAs (each acc reused 16 apart)
            #pragma unroll
            for (int mt = 0; mt < 4; mt++)
                #pragma unroll
                for (int nt = 0; nt < 4; nt++)
                    mma16816(acc[mt][nt], a[mt],
                             blo[nt >> 1][(nt & 1) * 2], blo[nt >> 1][(nt & 1) * 2 + 1]);

            // Pass 3: lh — reload A from lo, 16 independent MMAs
            #pragma unroll
            for (int mt = 0; mt < 4; mt++)
                ldsm4(a[mt], uAlo + a_off + (uint32_t)mt * 16 * ROWB + kb);
            #pragma unroll
            for (int mt = 0; mt < 4; mt++)
                #pragma unroll
                for (int nt = 0; nt < 4; nt++)
                    mma16816(acc[mt][nt], a[mt],
                             bhi[nt >> 1][(nt & 1) * 2], bhi[nt >> 1][(nt & 1) * 2 + 1]);
        }
    }

    // Epilogue: l2 -> 5-kernel sum via one exp + 4 squarings.
    // Accumulate in fp32 (all-positive partials), convert to double once.
    float cscale = g_scale;
    int r0 = wy * 64 + (lane >> 2);
    int c0 = wx * 32 + 2 * (lane & 3);
    float psum[4] = {0.0f, 0.0f, 0.0f, 0.0f};
    #pragma unroll
    for (int mt = 0; mt < 4; mt++) {
        #pragma unroll
        for (int nt = 0; nt < 4; nt++) {
            #pragma unroll
            for (int e = 0; e < 4; e++) {
                int i = r0 + mt * 16 + ((e >> 1) << 3);
                int j = c0 + nt * 8 + (e & 1);
                float l2 = fmaxf(sqa[i] + sqb[j] - 2.0f * acc[mt][nt][e], 0.0f);
                float ex = __expf(-l2 * cscale);
                float s  = ex;
                float p  = ex;
                p *= p; s += p;   // e^2
                p *= p; s += p;   // e^4
                p *= p; s += p;   // e^8
                p *= p; s += p;   // e^16
                psum[mt] += s;
            }
        }
    }
    double local = (double)((psum[0] + psum[1]) + (psum[2] + psum[3]));

    // Tile weight: sign from halves, x2 for off-diagonal (mirror tile)
    double w = ((bi < NT / 2) == (bj < NT / 2)) ? 1.0 : -1.0;
    if (bj > bi) w *= 2.0;
    local *= w;

    dred[tid] = local;
    __syncthreads();
    #pragma unroll
    for (int s = 128; s > 0; s >>= 1) {
        if (tid < s) dred[tid] += dred[tid + s];
        __syncthreads();
    }
    if (tid == 0) atomicAdd(&g_result, dred[0]);
}

// ---------------------------------------------------------------------------
__global__ void finalize_kernel(float* __restrict__ out) {
    out[0] = (float)(g_result * (1.0 / ((double)BROWS * (double)BROWS)));
}

extern "C" void kernel_launch(void* const* d_in, const int* in_sizes, int n_in,
                              void* d_out, int out_size) {
    const float* src = (const float*)d_in[0];
    const float* tgt = (const float*)d_in[1];
    float* out = (float*)d_out;
    (void)in_sizes; (void)n_in; (void)out_size;

    cudaFuncSetAttribute(pair5_kernel,
                         cudaFuncAttributeMaxDynamicSharedMemorySize, DYN_SMEM);

    zero_kernel<<<1, 512>>>();
    prep_kernel<<<256, 256>>>(src, tgt);
    bw_kernel<<<1, 1>>>();
    pair5_kernel<<<NTRI, 256, DYN_SMEM>>>();
    finalize_kernel<<<1, 1>>>(out);
}

// round 6
// speedup vs baseline: 3.3447x; 1.2512x over previous
#include <cuda_runtime.h>
#include <cuda_bf16.h>
#include <cstdint>

// Problem constants
#define NROWS 8192          // n = 2*B
#define BROWS 4096          // B
#define DDIM  256           // feature dim
#define BLK   128           // tile edge
#define NT    64            // NROWS/BLK
#define NTRI  (NT*(NT+1)/2) // 2080 upper-triangular tiles
#define KC    32            // k columns per chunk
#define NCH   (DDIM/KC)     // 8 chunks
#define ROWB  80            // smem row stride bytes (64B data + 16B pad)
#define MATB  (BLK*ROWB)    // 10240 B per matrix buffer
#define STAGEB (3*MATB)     // 30720 B per stage (Ahi,Bhi,Blo)
#define DYN_SMEM (2*STAGEB) // 61440 B

// Device scratch (no allocations allowed)
__device__ float  g_sq[NROWS];
__device__ double g_colsum[DDIM];
__device__ double g_S1;
__device__ double g_result;
__device__ float  g_scale;     // 1/(16*bandwidth)
__device__ __nv_bfloat16 g_hi[NROWS * DDIM];
__device__ __nv_bfloat16 g_lo[NROWS * DDIM];

// ---------------------------------------------------------------------------
__device__ __forceinline__ uint32_t smem_u32(const void* p) {
    uint32_t a;
    asm("{ .reg .u64 t; cvta.to.shared.u64 t, %1; cvt.u32.u64 %0, t; }"
        : "=r"(a) : "l"(p));
    return a;
}

__device__ __forceinline__ void ldsm4(uint32_t* r, uint32_t addr) {
    asm volatile("ldmatrix.sync.aligned.m8n8.x4.shared.b16 {%0,%1,%2,%3}, [%4];"
                 : "=r"(r[0]), "=r"(r[1]), "=r"(r[2]), "=r"(r[3]) : "r"(addr));
}

__device__ __forceinline__ void mma16816(float* c, const uint32_t* a,
                                         uint32_t b0, uint32_t b1) {
    asm volatile(
        "mma.sync.aligned.m16n8k16.row.col.f32.bf16.bf16.f32 "
        "{%0,%1,%2,%3}, {%4,%5,%6,%7}, {%8,%9}, {%0,%1,%2,%3};"
        : "+f"(c[0]), "+f"(c[1]), "+f"(c[2]), "+f"(c[3])
        : "r"(a[0]), "r"(a[1]), "r"(a[2]), "r"(a[3]), "r"(b0), "r"(b1));
}

#define CP_ASYNC16(dst, src) \
    asm volatile("cp.async.cg.shared.global [%0], [%1], 16;" \
                 :: "r"(dst), "l"(src) : "memory")
#define CP_COMMIT() asm volatile("cp.async.commit_group;" ::: "memory")
#define CP_WAIT0()  asm volatile("cp.async.wait_group 0;" ::: "memory")

// ---------------------------------------------------------------------------
__global__ void zero_kernel() {
    int t = blockIdx.x * blockDim.x + threadIdx.x;
    if (t < DDIM) g_colsum[t] = 0.0;
    if (t == 0)   g_S1 = 0.0;
}

// ---------------------------------------------------------------------------
// Warp-per-row prep: row norms (shfl reduce), column sums (smem reduce, one
// atomic per column per block), total sumsq, bf16 hi/lo split.
__global__ void prep_kernel(const float* __restrict__ src,
                            const float* __restrict__ tgt) {
    __shared__ double csum_s[8][DDIM];
    int tid  = threadIdx.x;
    int lane = tid & 31;
    int w    = tid >> 5;
    int b    = blockIdx.x;

    double csum[8] = {0, 0, 0, 0, 0, 0, 0, 0};
    double s1 = 0.0;

    #pragma unroll
    for (int i = 0; i < 4; i++) {
        int r = b * 32 + w * 4 + i;
        const float* row = (r < BROWS) ? (src + (size_t)r * DDIM)
                                       : (tgt + (size_t)(r - BROWS) * DDIM);
        float sq = 0.0f;
        #pragma unroll
        for (int k = 0; k < 8; k++) {
            int col = lane + 32 * k;
            float x = row[col];
            sq = fmaf(x, x, sq);
            csum[k] += (double)x;
            __nv_bfloat16 h = __float2bfloat16(x);
            g_hi[(size_t)r * DDIM + col] = h;
            g_lo[(size_t)r * DDIM + col] = __float2bfloat16(x - __bfloat162float(h));
        }
        #pragma unroll
        for (int s = 16; s > 0; s >>= 1) sq += __shfl_xor_sync(0xFFFFFFFFu, sq, s);
        if (lane == 0) { g_sq[r] = sq; s1 += (double)sq; }
    }

    #pragma unroll
    for (int k = 0; k < 8; k++) csum_s[w][lane + 32 * k] = csum[k];
    __syncthreads();
    double t = 0.0;
    #pragma unroll
    for (int w2 = 0; w2 < 8; w2++) t += csum_s[w2][tid];
    atomicAdd(&g_colsum[tid], t);
    if (lane == 0) atomicAdd(&g_S1, s1);
}

// ---------------------------------------------------------------------------
__global__ void bw_kernel() {
    double ss = 0.0;
    for (int d = 0; d < DDIM; d++) {
        double c = g_colsum[d];
        ss += c * c;
    }
    const double n = (double)NROWS;
    double sum_l2 = 2.0 * n * g_S1 - 2.0 * ss;
    double bw = sum_l2 / (n * n - n) / 4.0;   // / KERNEL_MUL^(KERNEL_NUM/2)
    g_scale = (float)(1.0 / (bw * 16.0));     // largest sigma = bw*2^4
    g_result = 0.0;
}

// ---------------------------------------------------------------------------
// Issue 6 cp.async (16B) per thread: one KC-chunk of 3 matrices (Ahi,Bhi,Blo).
__device__ __forceinline__ void prefetch_chunk(
    uint32_t sbase, const __nv_bfloat16* Ah,
    const __nv_bfloat16* Bh, const __nv_bfloat16* Bl, int k0, int tid) {
    #pragma unroll
    for (int l = 0; l < 2; l++) {
        int f   = tid + l * 256;      // 0..511
        int r   = f >> 2;
        int c16 = f & 3;
        uint32_t so = (uint32_t)r * ROWB + (uint32_t)c16 * 16;
        size_t  go = (size_t)r * DDIM + k0 + c16 * 8;
        CP_ASYNC16(sbase + 0 * MATB + so, (const void*)(Ah + go));
        CP_ASYNC16(sbase + 1 * MATB + so, (const void*)(Bh + go));
        CP_ASYNC16(sbase + 2 * MATB + so, (const void*)(Bl + go));
    }
}

// ---------------------------------------------------------------------------
// HMMA pair kernel: 128x128 tile per CTA, split-bf16 2-product mma.sync
// (hh + hl; lh term dropped — error ~1e-4 abs in dot, far under budget),
// cp.async double-buffered K-chunks, de-interleaved MMA passes.
__global__ void __launch_bounds__(256, 2)
pair6_kernel() {
    extern __shared__ __align__(16) char dyn[];
    __shared__ float  sqa[BLK];
    __shared__ float  sqb[BLK];
    __shared__ double dred[256];

    int tid  = threadIdx.x;
    int lane = tid & 31;
    int wid  = tid >> 5;
    int wy   = wid >> 2;      // 0..1
    int wx   = wid & 3;       // 0..3

    // Decode triangular tile index -> (bi, bj), bj >= bi
    int rem = blockIdx.x;
    int bi = 0;
    while (rem >= NT - bi) { rem -= NT - bi; bi++; }
    int bj = bi + rem;

    const __nv_bfloat16* Ah = g_hi + (size_t)bi * BLK * DDIM;
    const __nv_bfloat16* Bh = g_hi + (size_t)bj * BLK * DDIM;
    const __nv_bfloat16* Bl = g_lo + (size_t)bj * BLK * DDIM;

    if (tid < BLK) {
        sqa[tid] = g_sq[bi * BLK + tid];
        sqb[tid] = g_sq[bj * BLK + tid];
    }

    float acc[4][4][4];
    #pragma unroll
    for (int mt = 0; mt < 4; mt++)
        #pragma unroll
        for (int nt = 0; nt < 4; nt++)
            #pragma unroll
            for (int e = 0; e < 4; e++) acc[mt][nt][e] = 0.0f;

    uint32_t dynb = smem_u32(dyn);

    // Per-lane ldmatrix offsets (bytes) within a matrix buffer
    uint32_t a_off = (uint32_t)(wy * 64 + (lane & 15)) * ROWB + ((lane >> 4) << 4);
    uint32_t b_off = (uint32_t)(wx * 32 + (lane & 7) + ((lane >> 4) << 3)) * ROWB
                   + (((lane >> 3) & 1) << 4);

    prefetch_chunk(dynb, Ah, Bh, Bl, 0, tid);
    CP_COMMIT();

    for (int c = 0; c < NCH; c++) {
        CP_WAIT0();
        __syncthreads();
        if (c + 1 < NCH) {
            prefetch_chunk(dynb + ((c + 1) & 1) * STAGEB, Ah, Bh, Bl,
                           (c + 1) * KC, tid);
            CP_COMMIT();
        }

        uint32_t ub   = dynb + (c & 1) * STAGEB;
        uint32_t uAhi = ub;
        uint32_t uBhi = ub + MATB;
        uint32_t uBlo = ub + 2 * MATB;

        #pragma unroll
        for (int ks = 0; ks < 2; ks++) {
            uint32_t kb = (uint32_t)ks * 32;    // 16 bf16 = 32 bytes

            uint32_t bhi[2][4], blo[2][4];
            #pragma unroll
            for (int bp = 0; bp < 2; bp++) {
                uint32_t off = b_off + (uint32_t)bp * 16 * ROWB + kb;
                ldsm4(bhi[bp], uBhi + off);
                ldsm4(blo[bp], uBlo + off);
            }

            uint32_t a[4][4];
            #pragma unroll
            for (int mt = 0; mt < 4; mt++)
                ldsm4(a[mt], uAhi + a_off + (uint32_t)mt * 16 * ROWB + kb);

            // Pass 1: hh — 16 independent MMAs
            #pragma unroll
            for (int mt = 0; mt < 4; mt++)
                #pragma unroll
                for (int nt = 0; nt < 4; nt++)
                    mma16816(acc[mt][nt], a[mt],
                             bhi[nt >> 1][(nt & 1) * 2], bhi[nt >> 1][(nt & 1) * 2 + 1]);

            // Pass 2: hl — 16 independent MMAs (acc reuse distance 16)
            #pragma unroll
            for (int mt = 0; mt < 4; mt++)
                #pragma unroll
                for (int nt = 0; nt < 4; nt++)
                    mma16816(acc[mt][nt], a[mt],
                             blo[nt >> 1][(nt & 1) * 2], blo[nt >> 1][(nt & 1) * 2 + 1]);
        }
    }

    // Epilogue: l2 -> 5-kernel sum via one exp + 4 squarings.
    // Accumulate in fp32 (all-positive partials), convert to double once.
    float cscale = g_scale;
    int r0 = wy * 64 + (lane >> 2);
    int c0 = wx * 32 + 2 * (lane & 3);
    float psum[4] = {0.0f, 0.0f, 0.0f, 0.0f};
    #pragma unroll
    for (int mt = 0; mt < 4; mt++) {
        #pragma unroll
        for (int nt = 0; nt < 4; nt++) {
            #pragma unroll
            for (int e = 0; e < 4; e++) {
                int i = r0 + mt * 16 + ((e >> 1) << 3);
                int j = c0 + nt * 8 + (e & 1);
                float l2 = fmaxf(sqa[i] + sqb[j] - 2.0f * acc[mt][nt][e], 0.0f);
                float ex = __expf(-l2 * cscale);
                float s  = ex;
                float p  = ex;
                p *= p; s += p;   // e^2
                p *= p; s += p;   // e^4
                p *= p; s += p;   // e^8
                p *= p; s += p;   // e^16
                psum[mt] += s;
            }
        }
    }
    double local = (double)((psum[0] + psum[1]) + (psum[2] + psum[3]));

    // Tile weight: sign from halves, x2 for off-diagonal (mirror tile)
    double w = ((bi < NT / 2) == (bj < NT / 2)) ? 1.0 : -1.0;
    if (bj > bi) w *= 2.0;
    local *= w;

    dred[tid] = local;
    __syncthreads();
    #pragma unroll
    for (int s = 128; s > 0; s >>= 1) {
        if (tid < s) dred[tid] += dred[tid + s];
        __syncthreads();
    }
    if (tid == 0) atomicAdd(&g_result, dred[0]);
}

// ---------------------------------------------------------------------------
__global__ void finalize_kernel(float* __restrict__ out) {
    out[0] = (float)(g_result * (1.0 / ((double)BROWS * (double)BROWS)));
}

extern "C" void kernel_launch(void* const* d_in, const int* in_sizes, int n_in,
                              void* d_out, int out_size) {
    const float* src = (const float*)d_in[0];
    const float* tgt = (const float*)d_in[1];
    float* out = (float*)d_out;
    (void)in_sizes; (void)n_in; (void)out_size;

    cudaFuncSetAttribute(pair6_kernel,
                         cudaFuncAttributeMaxDynamicSharedMemorySize, DYN_SMEM);

    zero_kernel<<<1, 512>>>();
    prep_kernel<<<256, 256>>>(src, tgt);
    bw_kernel<<<1, 1>>>();
    pair6_kernel<<<NTRI, 256, DYN_SMEM>>>();
    finalize_kernel<<<1, 1>>>(out);
}

// round 7
// speedup vs baseline: 3.6667x; 1.0963x over previous
#include <cuda_runtime.h>
#include <cuda_bf16.h>
#include <cstdint>

// Problem constants
#define NROWS 8192          // n = 2*B
#define BROWS 4096          // B
#define DDIM  256           // feature dim
#define BLK   128           // tile edge
#define NT    64            // NROWS/BLK
#define NTRI  (NT*(NT+1)/2) // 2080 upper-triangular tiles
#define KC    32            // k columns per chunk
#define NCH   (DDIM/KC)     // 8 chunks
#define ROWB  80            // smem row stride bytes (64B data + 16B pad)
#define MATB  (BLK*ROWB)    // 10240 B per matrix buffer
#define STAGEB (3*MATB)     // 30720 B per stage (Ahi,Bhi,Blo)
#define NSTAGE 3
#define DYN_SMEM (NSTAGE*STAGEB) // 92160 B

// Device scratch (no allocations allowed)
__device__ float  g_sq[NROWS];
__device__ double g_colsum[DDIM];
__device__ double g_S1;
__device__ double g_result;
__device__ float  g_scale;     // 1/(16*bandwidth)
__device__ __nv_bfloat16 g_hi[NROWS * DDIM];
__device__ __nv_bfloat16 g_lo[NROWS * DDIM];

// ---------------------------------------------------------------------------
__device__ __forceinline__ uint32_t smem_u32(const void* p) {
    uint32_t a;
    asm("{ .reg .u64 t; cvta.to.shared.u64 t, %1; cvt.u32.u64 %0, t; }"
        : "=r"(a) : "l"(p));
    return a;
}

__device__ __forceinline__ void ldsm4(uint32_t* r, uint32_t addr) {
    asm volatile("ldmatrix.sync.aligned.m8n8.x4.shared.b16 {%0,%1,%2,%3}, [%4];"
                 : "=r"(r[0]), "=r"(r[1]), "=r"(r[2]), "=r"(r[3]) : "r"(addr));
}

__device__ __forceinline__ void mma16816(float* c, const uint32_t* a,
                                         uint32_t b0, uint32_t b1) {
    asm volatile(
        "mma.sync.aligned.m16n8k16.row.col.f32.bf16.bf16.f32 "
        "{%0,%1,%2,%3}, {%4,%5,%6,%7}, {%8,%9}, {%0,%1,%2,%3};"
        : "+f"(c[0]), "+f"(c[1]), "+f"(c[2]), "+f"(c[3])
        : "r"(a[0]), "r"(a[1]), "r"(a[2]), "r"(a[3]), "r"(b0), "r"(b1));
}

#define CP_ASYNC16(dst, src) \
    asm volatile("cp.async.cg.shared.global [%0], [%1], 16;" \
                 :: "r"(dst), "l"(src) : "memory")
#define CP_COMMIT() asm volatile("cp.async.commit_group;" ::: "memory")
#define CP_WAIT1()  asm volatile("cp.async.wait_group 1;" ::: "memory")

// ---------------------------------------------------------------------------
__global__ void zero_kernel() {
    int t = blockIdx.x * blockDim.x + threadIdx.x;
    if (t < DDIM) g_colsum[t] = 0.0;
    if (t == 0)   g_S1 = 0.0;
}

// ---------------------------------------------------------------------------
// Warp-per-row prep: row norms (shfl reduce), fp32 per-block column partials
// (double only at the one atomic per column), total sumsq, bf16 hi/lo split
// with float2 loads / bf16x2 stores.
__global__ void prep_kernel(const float* __restrict__ src,
                            const float* __restrict__ tgt) {
    __shared__ float csum_s[8][DDIM];
    int tid  = threadIdx.x;
    int lane = tid & 31;
    int w    = tid >> 5;
    int b    = blockIdx.x;

    float csum[8] = {0, 0, 0, 0, 0, 0, 0, 0};
    double s1 = 0.0;

    #pragma unroll
    for (int i = 0; i < 4; i++) {
        int r = b * 32 + w * 4 + i;
        const float2* row = (const float2*)((r < BROWS)
                            ? (src + (size_t)r * DDIM)
                            : (tgt + (size_t)(r - BROWS) * DDIM));
        float sq = 0.0f;
        #pragma unroll
        for (int k = 0; k < 4; k++) {
            int idx = lane + 32 * k;            // float2 index 0..127
            float2 x = row[idx];
            sq = fmaf(x.x, x.x, sq);
            sq = fmaf(x.y, x.y, sq);
            csum[2 * k]     += x.x;
            csum[2 * k + 1] += x.y;
            __nv_bfloat16 h0 = __float2bfloat16(x.x);
            __nv_bfloat16 h1 = __float2bfloat16(x.y);
            __nv_bfloat162 hv; hv.x = h0; hv.y = h1;
            __nv_bfloat162 lv;
            lv.x = __float2bfloat16(x.x - __bfloat162float(h0));
            lv.y = __float2bfloat16(x.y - __bfloat162float(h1));
            ((__nv_bfloat162*)(g_hi + (size_t)r * DDIM))[idx] = hv;
            ((__nv_bfloat162*)(g_lo + (size_t)r * DDIM))[idx] = lv;
        }
        #pragma unroll
        for (int s = 16; s > 0; s >>= 1) sq += __shfl_xor_sync(0xFFFFFFFFu, sq, s);
        if (lane == 0) { g_sq[r] = sq; s1 += (double)sq; }
    }

    // csum[j] belongs to column 2*(j/2)*?? -> column = 64*k + 2*lane (+1)
    #pragma unroll
    for (int k = 0; k < 4; k++) {
        csum_s[w][64 * k + 2 * lane]     = csum[2 * k];
        csum_s[w][64 * k + 2 * lane + 1] = csum[2 * k + 1];
    }
    __syncthreads();
    float t = 0.0f;
    #pragma unroll
    for (int w2 = 0; w2 < 8; w2++) t += csum_s[w2][tid];
    atomicAdd(&g_colsum[tid], (double)t);
    if (lane == 0) atomicAdd(&g_S1, s1);
}

// ---------------------------------------------------------------------------
__global__ void bw_kernel() {
    double ss = 0.0;
    for (int d = 0; d < DDIM; d++) {
        double c = g_colsum[d];
        ss += c * c;
    }
    const double n = (double)NROWS;
    double sum_l2 = 2.0 * n * g_S1 - 2.0 * ss;
    double bw = sum_l2 / (n * n - n) / 4.0;   // / KERNEL_MUL^(KERNEL_NUM/2)
    g_scale = (float)(1.0 / (bw * 16.0));     // largest sigma = bw*2^4
    g_result = 0.0;
}

// ---------------------------------------------------------------------------
// Issue 6 cp.async (16B) per thread: one KC-chunk of 3 matrices (Ahi,Bhi,Blo).
__device__ __forceinline__ void prefetch_chunk(
    uint32_t sbase, const __nv_bfloat16* Ah,
    const __nv_bfloat16* Bh, const __nv_bfloat16* Bl, int k0, int tid) {
    #pragma unroll
    for (int l = 0; l < 2; l++) {
        int f   = tid + l * 256;      // 0..511
        int r   = f >> 2;
        int c16 = f & 3;
        uint32_t so = (uint32_t)r * ROWB + (uint32_t)c16 * 16;
        size_t  go = (size_t)r * DDIM + k0 + c16 * 8;
        CP_ASYNC16(sbase + 0 * MATB + so, (const void*)(Ah + go));
        CP_ASYNC16(sbase + 1 * MATB + so, (const void*)(Bh + go));
        CP_ASYNC16(sbase + 2 * MATB + so, (const void*)(Bl + go));
    }
}

// ---------------------------------------------------------------------------
// HMMA pair kernel: 128x128 tile per CTA, split-bf16 2-product mma.sync
// (hh + hl), 3-stage cp.async ring (wait_group 1), de-interleaved MMA passes.
__global__ void __launch_bounds__(256, 2)
pair7_kernel() {
    extern __shared__ __align__(16) char dyn[];
    __shared__ float  sqa[BLK];
    __shared__ float  sqb[BLK];
    __shared__ double dred[256];

    int tid  = threadIdx.x;
    int lane = tid & 31;
    int wid  = tid >> 5;
    int wy   = wid >> 2;      // 0..1
    int wx   = wid & 3;       // 0..3

    // Decode triangular tile index -> (bi, bj), bj >= bi
    int rem = blockIdx.x;
    int bi = 0;
    while (rem >= NT - bi) { rem -= NT - bi; bi++; }
    int bj = bi + rem;

    const __nv_bfloat16* Ah = g_hi + (size_t)bi * BLK * DDIM;
    const __nv_bfloat16* Bh = g_hi + (size_t)bj * BLK * DDIM;
    const __nv_bfloat16* Bl = g_lo + (size_t)bj * BLK * DDIM;

    if (tid < BLK) {
        sqa[tid] = g_sq[bi * BLK + tid];
        sqb[tid] = g_sq[bj * BLK + tid];
    }

    float acc[4][4][4];
    #pragma unroll
    for (int mt = 0; mt < 4; mt++)
        #pragma unroll
        for (int nt = 0; nt < 4; nt++)
            #pragma unroll
            for (int e = 0; e < 4; e++) acc[mt][nt][e] = 0.0f;

    uint32_t dynb = smem_u32(dyn);

    // Per-lane ldmatrix offsets (bytes) within a matrix buffer
    uint32_t a_off = (uint32_t)(wy * 64 + (lane & 15)) * ROWB + ((lane >> 4) << 4);
    uint32_t b_off = (uint32_t)(wx * 32 + (lane & 7) + ((lane >> 4) << 3)) * ROWB
                   + (((lane >> 3) & 1) << 4);

    // Prologue: 2 chunks in flight
    prefetch_chunk(dynb + 0 * STAGEB, Ah, Bh, Bl, 0, tid);
    CP_COMMIT();
    prefetch_chunk(dynb + 1 * STAGEB, Ah, Bh, Bl, KC, tid);
    CP_COMMIT();

    int stage = 0;
    for (int c = 0; c < NCH; c++) {
        CP_WAIT1();              // chunk c complete (<=1 younger group pending)
        __syncthreads();         // all warps: chunk c visible, stage c+2 free
        if (c + 2 < NCH) {
            int pstage = stage + 2;
            if (pstage >= NSTAGE) pstage -= NSTAGE;
            prefetch_chunk(dynb + pstage * STAGEB, Ah, Bh, Bl, (c + 2) * KC, tid);
        }
        CP_COMMIT();             // commit every iteration (empty groups OK)

        uint32_t ub   = dynb + stage * STAGEB;
        uint32_t uAhi = ub;
        uint32_t uBhi = ub + MATB;
        uint32_t uBlo = ub + 2 * MATB;
        if (++stage == NSTAGE) stage = 0;

        #pragma unroll
        for (int ks = 0; ks < 2; ks++) {
            uint32_t kb = (uint32_t)ks * 32;    // 16 bf16 = 32 bytes

            uint32_t bhi[2][4], blo[2][4];
            #pragma unroll
            for (int bp = 0; bp < 2; bp++) {
                uint32_t off = b_off + (uint32_t)bp * 16 * ROWB + kb;
                ldsm4(bhi[bp], uBhi + off);
                ldsm4(blo[bp], uBlo + off);
            }

            uint32_t a[4][4];
            #pragma unroll
            for (int mt = 0; mt < 4; mt++)
                ldsm4(a[mt], uAhi + a_off + (uint32_t)mt * 16 * ROWB + kb);

            // Pass 1: hh — 16 independent MMAs
            #pragma unroll
            for (int mt = 0; mt < 4; mt++)
                #pragma unroll
                for (int nt = 0; nt < 4; nt++)
                    mma16816(acc[mt][nt], a[mt],
                             bhi[nt >> 1][(nt & 1) * 2], bhi[nt >> 1][(nt & 1) * 2 + 1]);

            // Pass 2: hl — 16 independent MMAs (acc reuse distance 16)
            #pragma unroll
            for (int mt = 0; mt < 4; mt++)
                #pragma unroll
                for (int nt = 0; nt < 4; nt++)
                    mma16816(acc[mt][nt], a[mt],
                             blo[nt >> 1][(nt & 1) * 2], blo[nt >> 1][(nt & 1) * 2 + 1]);
        }
    }

    // Epilogue: l2 -> 5-kernel sum via one exp + 4 squarings.
    float cscale = g_scale;
    int r0 = wy * 64 + (lane >> 2);
    int c0 = wx * 32 + 2 * (lane & 3);
    float psum[4] = {0.0f, 0.0f, 0.0f, 0.0f};
    #pragma unroll
    for (int mt = 0; mt < 4; mt++) {
        #pragma unroll
        for (int nt = 0; nt < 4; nt++) {
            #pragma unroll
            for (int e = 0; e < 4; e++) {
                int i = r0 + mt * 16 + ((e >> 1) << 3);
                int j = c0 + nt * 8 + (e & 1);
                float l2 = fmaxf(sqa[i] + sqb[j] - 2.0f * acc[mt][nt][e], 0.0f);
                float ex = __expf(-l2 * cscale);
                float s  = ex;
                float p  = ex;
                p *= p; s += p;   // e^2
                p *= p; s += p;   // e^4
                p *= p; s += p;   // e^8
                p *= p; s += p;   // e^16
                psum[mt] += s;
            }
        }
    }
    double local = (double)((psum[0] + psum[1]) + (psum[2] + psum[3]));

    // Tile weight: sign from halves, x2 for off-diagonal (mirror tile)
    double w = ((bi < NT / 2) == (bj < NT / 2)) ? 1.0 : -1.0;
    if (bj > bi) w *= 2.0;
    local *= w;

    dred[tid] = local;
    __syncthreads();
    #pragma unroll
    for (int s = 128; s > 0; s >>= 1) {
        if (tid < s) dred[tid] += dred[tid + s];
        __syncthreads();
    }
    if (tid == 0) atomicAdd(&g_result, dred[0]);
}

// ---------------------------------------------------------------------------
__global__ void finalize_kernel(float* __restrict__ out) {
    out[0] = (float)(g_result * (1.0 / ((double)BROWS * (double)BROWS)));
}

extern "C" void kernel_launch(void* const* d_in, const int* in_sizes, int n_in,
                              void* d_out, int out_size) {
    const float* src = (const float*)d_in[0];
    const float* tgt = (const float*)d_in[1];
    float* out = (float*)d_out;
    (void)in_sizes; (void)n_in; (void)out_size;

    cudaFuncSetAttribute(pair7_kernel,
                         cudaFuncAttributeMaxDynamicSharedMemorySize, DYN_SMEM);

    zero_kernel<<<1, 512>>>();
    prep_kernel<<<256, 256>>>(src, tgt);
    bw_kernel<<<1, 1>>>();
    pair7_kernel<<<NTRI, 256, DYN_SMEM>>>();
    finalize_kernel<<<1, 1>>>(out);
}

// round 8
// speedup vs baseline: 5.6460x; 1.5398x over previous
#include <cuda_runtime.h>
#include <cuda_fp16.h>
#include <cstdint>

// Problem constants
#define NROWS 8192          // n = 2*B
#define BROWS 4096          // B
#define DDIM  256           // feature dim
#define BLK   128           // tile edge
#define NT    64            // NROWS/BLK
#define NTRI  (NT*(NT+1)/2) // 2080 upper-triangular tiles
#define KC    64            // k columns per chunk (128B of fp16)
#define NCH   (DDIM/KC)     // 4 chunks
#define ROWB  144           // smem row stride bytes (128B data + 16B pad)
#define MATB  (BLK*ROWB)    // 18432 B per matrix buffer
#define STAGEB (2*MATB)     // 36864 B per stage (A, B)
#define NSTAGE 3
#define DYN_SMEM (NSTAGE*STAGEB) // 110592 B

// Device scratch (no allocations allowed)
__device__ float  g_sq[NROWS];
__device__ double g_colsum[DDIM];
__device__ double g_S1;
__device__ double g_result;
__device__ float  g_scale;     // 1/(16*bandwidth)
__device__ __half g_h[NROWS * DDIM];

// ---------------------------------------------------------------------------
__device__ __forceinline__ uint32_t smem_u32(const void* p) {
    uint32_t a;
    asm("{ .reg .u64 t; cvta.to.shared.u64 t, %1; cvt.u32.u64 %0, t; }"
        : "=r"(a) : "l"(p));
    return a;
}

__device__ __forceinline__ void ldsm4(uint32_t* r, uint32_t addr) {
    asm volatile("ldmatrix.sync.aligned.m8n8.x4.shared.b16 {%0,%1,%2,%3}, [%4];"
                 : "=r"(r[0]), "=r"(r[1]), "=r"(r[2]), "=r"(r[3]) : "r"(addr));
}

__device__ __forceinline__ void mma16816(float* c, const uint32_t* a,
                                         uint32_t b0, uint32_t b1) {
    asm volatile(
        "mma.sync.aligned.m16n8k16.row.col.f32.f16.f16.f32 "
        "{%0,%1,%2,%3}, {%4,%5,%6,%7}, {%8,%9}, {%0,%1,%2,%3};"
        : "+f"(c[0]), "+f"(c[1]), "+f"(c[2]), "+f"(c[3])
        : "r"(a[0]), "r"(a[1]), "r"(a[2]), "r"(a[3]), "r"(b0), "r"(b1));
}

#define CP_ASYNC16(dst, src) \
    asm volatile("cp.async.cg.shared.global [%0], [%1], 16;" \
                 :: "r"(dst), "l"(src) : "memory")
#define CP_COMMIT() asm volatile("cp.async.commit_group;" ::: "memory")
#define CP_WAIT1()  asm volatile("cp.async.wait_group 1;" ::: "memory")

// ---------------------------------------------------------------------------
__global__ void zero_kernel() {
    int t = blockIdx.x * blockDim.x + threadIdx.x;
    if (t < DDIM) g_colsum[t] = 0.0;
    if (t == 0)   g_S1 = 0.0;
}

// ---------------------------------------------------------------------------
// Warp-per-row prep: row norms (shfl reduce), fp32 per-block column partials,
// total sumsq, fp16 conversion (float2 loads / half2 stores).
__global__ void prep_kernel(const float* __restrict__ src,
                            const float* __restrict__ tgt) {
    __shared__ float csum_s[8][DDIM];
    int tid  = threadIdx.x;
    int lane = tid & 31;
    int w    = tid >> 5;
    int b    = blockIdx.x;

    float csum[8] = {0, 0, 0, 0, 0, 0, 0, 0};
    double s1 = 0.0;

    #pragma unroll
    for (int i = 0; i < 4; i++) {
        int r = b * 32 + w * 4 + i;
        const float2* row = (const float2*)((r < BROWS)
                            ? (src + (size_t)r * DDIM)
                            : (tgt + (size_t)(r - BROWS) * DDIM));
        float sq = 0.0f;
        #pragma unroll
        for (int k = 0; k < 4; k++) {
            int idx = lane + 32 * k;            // float2 index 0..127
            float2 x = row[idx];
            sq = fmaf(x.x, x.x, sq);
            sq = fmaf(x.y, x.y, sq);
            csum[2 * k]     += x.x;
            csum[2 * k + 1] += x.y;
            ((half2*)(g_h + (size_t)r * DDIM))[idx] = __floats2half2_rn(x.x, x.y);
        }
        #pragma unroll
        for (int s = 16; s > 0; s >>= 1) sq += __shfl_xor_sync(0xFFFFFFFFu, sq, s);
        if (lane == 0) { g_sq[r] = sq; s1 += (double)sq; }
    }

    #pragma unroll
    for (int k = 0; k < 4; k++) {
        csum_s[w][64 * k + 2 * lane]     = csum[2 * k];
        csum_s[w][64 * k + 2 * lane + 1] = csum[2 * k + 1];
    }
    __syncthreads();
    float t = 0.0f;
    #pragma unroll
    for (int w2 = 0; w2 < 8; w2++) t += csum_s[w2][tid];
    atomicAdd(&g_colsum[tid], (double)t);
    if (lane == 0) atomicAdd(&g_S1, s1);
}

// ---------------------------------------------------------------------------
__global__ void bw_kernel() {
    double ss = 0.0;
    for (int d = 0; d < DDIM; d++) {
        double c = g_colsum[d];
        ss += c * c;
    }
    const double n = (double)NROWS;
    double sum_l2 = 2.0 * n * g_S1 - 2.0 * ss;
    double bw = sum_l2 / (n * n - n) / 4.0;   // / KERNEL_MUL^(KERNEL_NUM/2)
    g_scale = (float)(1.0 / (bw * 16.0));     // largest sigma = bw*2^4
    g_result = 0.0;
}

// ---------------------------------------------------------------------------
// Issue 8 cp.async (16B) per thread: one KC=64 chunk of A and B fp16 tiles.
__device__ __forceinline__ void prefetch_chunk(
    uint32_t sbase, const __half* A, const __half* B, int k0, int tid) {
    #pragma unroll
    for (int l = 0; l < 4; l++) {
        int f   = tid + l * 256;      // 0..1023
        int r   = f >> 3;             // row 0..127
        int c16 = f & 7;              // 16B group within 128B row
        uint32_t so = (uint32_t)r * ROWB + (uint32_t)c16 * 16;
        size_t  go = (size_t)r * DDIM + k0 + c16 * 8;
        CP_ASYNC16(sbase + so,        (const void*)(A + go));
        CP_ASYNC16(sbase + MATB + so, (const void*)(B + go));
    }
}

// ---------------------------------------------------------------------------
// HMMA pair kernel: 128x128 tile per CTA, single-product fp16 mma.sync,
// 3-stage cp.async ring over KC=64 chunks.
__global__ void __launch_bounds__(256, 2)
pair8_kernel() {
    extern __shared__ __align__(16) char dyn[];
    __shared__ float sqa[BLK];
    __shared__ float sqb[BLK];

    int tid  = threadIdx.x;
    int lane = tid & 31;
    int wid  = tid >> 5;
    int wy   = wid >> 2;      // 0..1
    int wx   = wid & 3;       // 0..3

    // Decode triangular tile index -> (bi, bj), bj >= bi
    int rem = blockIdx.x;
    int bi = 0;
    while (rem >= NT - bi) { rem -= NT - bi; bi++; }
    int bj = bi + rem;

    const __half* A = g_h + (size_t)bi * BLK * DDIM;
    const __half* B = g_h + (size_t)bj * BLK * DDIM;

    if (tid < BLK) {
        sqa[tid] = g_sq[bi * BLK + tid];
        sqb[tid] = g_sq[bj * BLK + tid];
    }

    float acc[4][4][4];
    #pragma unroll
    for (int mt = 0; mt < 4; mt++)
        #pragma unroll
        for (int nt = 0; nt < 4; nt++)
            #pragma unroll
            for (int e = 0; e < 4; e++) acc[mt][nt][e] = 0.0f;

    uint32_t dynb = smem_u32(dyn);

    // Per-lane ldmatrix offsets (bytes) within a matrix buffer
    uint32_t a_off = (uint32_t)(wy * 64 + (lane & 15)) * ROWB + ((lane >> 4) << 4);
    uint32_t b_off = (uint32_t)(wx * 32 + (lane & 7) + ((lane >> 4) << 3)) * ROWB
                   + (((lane >> 3) & 1) << 4);

    // Prologue: 2 chunks in flight
    prefetch_chunk(dynb + 0 * STAGEB, A, B, 0, tid);
    CP_COMMIT();
    prefetch_chunk(dynb + 1 * STAGEB, A, B, KC, tid);
    CP_COMMIT();

    int stage = 0;
    for (int c = 0; c < NCH; c++) {
        CP_WAIT1();              // chunk c complete (<=1 younger group pending)
        __syncthreads();         // chunk c visible to all; stage c+2 free
        if (c + 2 < NCH) {
            int pstage = stage + 2;
            if (pstage >= NSTAGE) pstage -= NSTAGE;
            prefetch_chunk(dynb + pstage * STAGEB, A, B, (c + 2) * KC, tid);
        }
        CP_COMMIT();             // commit every iteration (empty groups OK)

        uint32_t uA = dynb + stage * STAGEB;
        uint32_t uB = uA + MATB;
        if (++stage == NSTAGE) stage = 0;

        #pragma unroll
        for (int ks = 0; ks < 4; ks++) {
            uint32_t kb = (uint32_t)ks * 32;    // 16 fp16 = 32 bytes

            uint32_t bf[2][4];
            #pragma unroll
            for (int bp = 0; bp < 2; bp++)
                ldsm4(bf[bp], uB + b_off + (uint32_t)bp * 16 * ROWB + kb);

            uint32_t a[4][4];
            #pragma unroll
            for (int mt = 0; mt < 4; mt++)
                ldsm4(a[mt], uA + a_off + (uint32_t)mt * 16 * ROWB + kb);

            // 16 independent MMAs
            #pragma unroll
            for (int mt = 0; mt < 4; mt++)
                #pragma unroll
                for (int nt = 0; nt < 4; nt++)
                    mma16816(acc[mt][nt], a[mt],
                             bf[nt >> 1][(nt & 1) * 2], bf[nt >> 1][(nt & 1) * 2 + 1]);
        }
    }

    // Epilogue: l2 -> 5-kernel sum via one exp + 4 squarings.
    float cscale = g_scale;
    int r0 = wy * 64 + (lane >> 2);
    int c0 = wx * 32 + 2 * (lane & 3);
    float psum[4] = {0.0f, 0.0f, 0.0f, 0.0f};
    #pragma unroll
    for (int mt = 0; mt < 4; mt++) {
        #pragma unroll
        for (int nt = 0; nt < 4; nt++) {
            #pragma unroll
            for (int e = 0; e < 4; e++) {
                int i = r0 + mt * 16 + ((e >> 1) << 3);
                int j = c0 + nt * 8 + (e & 1);
                float l2 = fmaxf(sqa[i] + sqb[j] - 2.0f * acc[mt][nt][e], 0.0f);
                float ex = __expf(-l2 * cscale);
                float s  = ex;
                float p  = ex;
                p *= p; s += p;   // e^2
                p *= p; s += p;   // e^4
                p *= p; s += p;   // e^8
                p *= p; s += p;   // e^16
                psum[mt] += s;
            }
        }
    }
    double local = (double)((psum[0] + psum[1]) + (psum[2] + psum[3]));

    // Tile weight: sign from halves, x2 for off-diagonal (mirror tile)
    double w = ((bi < NT / 2) == (bj < NT / 2)) ? 1.0 : -1.0;
    if (bj > bi) w *= 2.0;
    local *= w;

    // Warp shfl reduce (double) + one atomic per warp
    #pragma unroll
    for (int s = 16; s > 0; s >>= 1)
        local += __shfl_xor_sync(0xFFFFFFFFu, local, s);
    if (lane == 0) atomicAdd(&g_result, local);
}

// ---------------------------------------------------------------------------
__global__ void finalize_kernel(float* __restrict__ out) {
    out[0] = (float)(g_result * (1.0 / ((double)BROWS * (double)BROWS)));
}

extern "C" void kernel_launch(void* const* d_in, const int* in_sizes, int n_in,
                              void* d_out, int out_size) {
    const float* src = (const float*)d_in[0];
    const float* tgt = (const float*)d_in[1];
    float* out = (float*)d_out;
    (void)in_sizes; (void)n_in; (void)out_size;

    cudaFuncSetAttribute(pair8_kernel,
                         cudaFuncAttributeMaxDynamicSharedMemorySize, DYN_SMEM);

    zero_kernel<<<1, 512>>>();
    prep_kernel<<<256, 256>>>(src, tgt);
    bw_kernel<<<1, 1>>>();
    pair8_kernel<<<NTRI, 256, DYN_SMEM>>>();
    finalize_kernel<<<1, 1>>>(out);
}

// round 9
// speedup vs baseline: 6.2447x; 1.1060x over previous
#include <cuda_runtime.h>
#include <cuda_fp16.h>
#include <cstdint>

// Problem constants
#define NROWS 8192          // n = 2*B
#define BROWS 4096          // B
#define DDIM  256           // feature dim
#define BLK   128           // tile edge
#define NT    64            // NROWS/BLK
#define NTRI  (NT*(NT+1)/2) // 2080 upper-triangular tiles
#define KC    64            // k columns per chunk (128B of fp16)
#define NCH   (DDIM/KC)     // 4 chunks
#define ROWB  144           // smem row stride bytes (128B data + 16B pad)
#define MATB  (BLK*ROWB)    // 18432 B per matrix buffer
#define STAGEB (2*MATB)     // 36864 B per stage (A, B)
#define NSTAGE 3
#define DYN_SMEM (NSTAGE*STAGEB) // 110592 B
#define PREPB 256           // prep blocks

// Device scratch (no allocations allowed)
__device__ float  g_sq[NROWS];
__device__ float  g_colpart[PREPB][DDIM];
__device__ double g_s1part[PREPB];
__device__ double g_result;
__device__ float  g_scale;     // 1/(16*bandwidth)
__device__ __half g_h[NROWS * DDIM];
__device__ unsigned int g_prep_count = 0;
__device__ unsigned int g_pair_count = 0;

// ---------------------------------------------------------------------------
__device__ __forceinline__ uint32_t smem_u32(const void* p) {
    uint32_t a;
    asm("{ .reg .u64 t; cvta.to.shared.u64 t, %1; cvt.u32.u64 %0, t; }"
        : "=r"(a) : "l"(p));
    return a;
}

__device__ __forceinline__ void ldsm4(uint32_t* r, uint32_t addr) {
    asm volatile("ldmatrix.sync.aligned.m8n8.x4.shared.b16 {%0,%1,%2,%3}, [%4];"
                 : "=r"(r[0]), "=r"(r[1]), "=r"(r[2]), "=r"(r[3]) : "r"(addr));
}

__device__ __forceinline__ void mma16816(float* c, const uint32_t* a,
                                         uint32_t b0, uint32_t b1) {
    asm volatile(
        "mma.sync.aligned.m16n8k16.row.col.f32.f16.f16.f32 "
        "{%0,%1,%2,%3}, {%4,%5,%6,%7}, {%8,%9}, {%0,%1,%2,%3};"
        : "+f"(c[0]), "+f"(c[1]), "+f"(c[2]), "+f"(c[3])
        : "r"(a[0]), "r"(a[1]), "r"(a[2]), "r"(a[3]), "r"(b0), "r"(b1));
}

__device__ __forceinline__ float ex2f(float x) {
    float r;
    asm("ex2.approx.ftz.f32 %0, %1;" : "=f"(r) : "f"(x));
    return r;
}

#define CP_ASYNC16(dst, src) \
    asm volatile("cp.async.cg.shared.global [%0], [%1], 16;" \
                 :: "r"(dst), "l"(src) : "memory")
#define CP_COMMIT() asm volatile("cp.async.commit_group;" ::: "memory")
#define CP_WAIT1()  asm volatile("cp.async.wait_group 1;" ::: "memory")

// ---------------------------------------------------------------------------
// Fused prep: row norms, per-block column partials + s1 partials, fp16 cast.
// The LAST block to finish reduces partials -> bandwidth -> g_scale, and
// zeroes g_result for the pair kernel. Self-resetting counter (atomicInc
// wrap) keeps the kernel graph-replayable.
__global__ void prep_kernel(const float* __restrict__ src,
                            const float* __restrict__ tgt) {
    __shared__ float  csum_s[8][DDIM];
    __shared__ double s1_s[8];
    __shared__ double red_d[256];
    __shared__ bool   is_last;

    int tid  = threadIdx.x;
    int lane = tid & 31;
    int w    = tid >> 5;
    int b    = blockIdx.x;

    float csum[8] = {0, 0, 0, 0, 0, 0, 0, 0};
    double s1 = 0.0;

    #pragma unroll
    for (int i = 0; i < 4; i++) {
        int r = b * 32 + w * 4 + i;
        const float2* row = (const float2*)((r < BROWS)
                            ? (src + (size_t)r * DDIM)
                            : (tgt + (size_t)(r - BROWS) * DDIM));
        float sq = 0.0f;
        #pragma unroll
        for (int k = 0; k < 4; k++) {
            int idx = lane + 32 * k;            // float2 index 0..127
            float2 x = row[idx];
            sq = fmaf(x.x, x.x, sq);
            sq = fmaf(x.y, x.y, sq);
            csum[2 * k]     += x.x;
            csum[2 * k + 1] += x.y;
            ((half2*)(g_h + (size_t)r * DDIM))[idx] = __floats2half2_rn(x.x, x.y);
        }
        #pragma unroll
        for (int s = 16; s > 0; s >>= 1) sq += __shfl_xor_sync(0xFFFFFFFFu, sq, s);
        if (lane == 0) { g_sq[r] = sq; s1 += (double)sq; }
    }

    #pragma unroll
    for (int k = 0; k < 4; k++) {
        csum_s[w][64 * k + 2 * lane]     = csum[2 * k];
        csum_s[w][64 * k + 2 * lane + 1] = csum[2 * k + 1];
    }
    if (lane == 0) s1_s[w] = s1;
    __syncthreads();

    // Per-block partials to global
    float t = 0.0f;
    #pragma unroll
    for (int w2 = 0; w2 < 8; w2++) t += csum_s[w2][tid];
    g_colpart[b][tid] = t;
    if (tid == 0) {
        double bs1 = 0.0;
        #pragma unroll
        for (int w2 = 0; w2 < 8; w2++) bs1 += s1_s[w2];
        g_s1part[b] = bs1;
    }

    // Last-block reduction (threadFenceReduction pattern)
    __threadfence();
    __syncthreads();
    if (tid == 0) {
        unsigned int old = atomicInc(&g_prep_count, PREPB - 1);
        is_last = (old == PREPB - 1);
    }
    __syncthreads();
    if (!is_last) return;
    __threadfence();

    // Column sums: thread t owns column t
    float cs = 0.0f;
    for (int b2 = 0; b2 < PREPB; b2++) cs += g_colpart[b2][tid];
    double ssq = (double)cs * (double)cs;
    double s1v = g_s1part[tid];

    red_d[tid] = ssq;
    __syncthreads();
    #pragma unroll
    for (int s = 128; s > 0; s >>= 1) {
        if (tid < s) red_d[tid] += red_d[tid + s];
        __syncthreads();
    }
    double ss = red_d[0];
    __syncthreads();
    red_d[tid] = s1v;
    __syncthreads();
    #pragma unroll
    for (int s = 128; s > 0; s >>= 1) {
        if (tid < s) red_d[tid] += red_d[tid + s];
        __syncthreads();
    }
    if (tid == 0) {
        double S1 = red_d[0];
        const double n = (double)NROWS;
        double sum_l2 = 2.0 * n * S1 - 2.0 * ss;
        double bw = sum_l2 / (n * n - n) / 4.0;   // / KERNEL_MUL^(KERNEL_NUM/2)
        g_scale = (float)(1.0 / (bw * 16.0));     // largest sigma = bw*2^4
        g_result = 0.0;
    }
}

// ---------------------------------------------------------------------------
// Issue 8 cp.async (16B) per thread: one KC=64 chunk of A and B fp16 tiles.
__device__ __forceinline__ void prefetch_chunk(
    uint32_t sbase, const __half* A, const __half* B, int k0, int tid) {
    #pragma unroll
    for (int l = 0; l < 4; l++) {
        int f   = tid + l * 256;      // 0..1023
        int r   = f >> 3;             // row 0..127
        int c16 = f & 7;              // 16B group within 128B row
        uint32_t so = (uint32_t)r * ROWB + (uint32_t)c16 * 16;
        size_t  go = (size_t)r * DDIM + k0 + c16 * 8;
        CP_ASYNC16(sbase + so,        (const void*)(A + go));
        CP_ASYNC16(sbase + MATB + so, (const void*)(B + go));
    }
}

// ---------------------------------------------------------------------------
// HMMA pair kernel: 128x128 tile per CTA, single-product fp16 mma.sync,
// 3-stage cp.async ring; fused finalize in the last CTA.
__global__ void __launch_bounds__(256, 2)
pair9_kernel(float* __restrict__ out) {
    extern __shared__ __align__(16) char dyn[];
    __shared__ float sqa[BLK];
    __shared__ float sqb[BLK];

    int tid  = threadIdx.x;
    int lane = tid & 31;
    int wid  = tid >> 5;
    int wy   = wid >> 2;      // 0..1
    int wx   = wid & 3;       // 0..3

    // Closed-form triangular decode: bi = row of tile, bj >= bi
    int rem = blockIdx.x;
    int bi = (int)((2.0f * NT + 1.0f
              - sqrtf((float)((2 * NT + 1) * (2 * NT + 1) - 8 * rem))) * 0.5f);
    while (bi * NT - bi * (bi - 1) / 2 > rem) bi--;
    while ((bi + 1) * NT - (bi + 1) * bi / 2 <= rem) bi++;
    int bj = bi + rem - (bi * NT - bi * (bi - 1) / 2);

    const __half* A = g_h + (size_t)bi * BLK * DDIM;
    const __half* B = g_h + (size_t)bj * BLK * DDIM;

    uint32_t dynb = smem_u32(dyn);

    // Prologue: 2 chunks in flight
    prefetch_chunk(dynb + 0 * STAGEB, A, B, 0, tid);
    CP_COMMIT();
    prefetch_chunk(dynb + 1 * STAGEB, A, B, KC, tid);
    CP_COMMIT();

    if (tid < BLK) {
        sqa[tid] = g_sq[bi * BLK + tid];
        sqb[tid] = g_sq[bj * BLK + tid];
    }

    float acc[4][4][4];
    #pragma unroll
    for (int mt = 0; mt < 4; mt++)
        #pragma unroll
        for (int nt = 0; nt < 4; nt++)
            #pragma unroll
            for (int e = 0; e < 4; e++) acc[mt][nt][e] = 0.0f;

    // Per-lane ldmatrix offsets (bytes) within a matrix buffer
    uint32_t a_off = (uint32_t)(wy * 64 + (lane & 15)) * ROWB + ((lane >> 4) << 4);
    uint32_t b_off = (uint32_t)(wx * 32 + (lane & 7) + ((lane >> 4) << 3)) * ROWB
                   + (((lane >> 3) & 1) << 4);

    int stage = 0;
    for (int c = 0; c < NCH; c++) {
        CP_WAIT1();              // chunk c complete (<=1 younger group pending)
        __syncthreads();         // chunk c visible to all; stage c+2 free
        if (c + 2 < NCH) {
            int pstage = stage + 2;
            if (pstage >= NSTAGE) pstage -= NSTAGE;
            prefetch_chunk(dynb + pstage * STAGEB, A, B, (c + 2) * KC, tid);
        }
        CP_COMMIT();             // commit every iteration (empty groups OK)

        uint32_t uA = dynb + stage * STAGEB;
        uint32_t uB = uA + MATB;
        if (++stage == NSTAGE) stage = 0;

        #pragma unroll
        for (int ks = 0; ks < 4; ks++) {
            uint32_t kb = (uint32_t)ks * 32;    // 16 fp16 = 32 bytes

            uint32_t bf[2][4];
            #pragma unroll
            for (int bp = 0; bp < 2; bp++)
                ldsm4(bf[bp], uB + b_off + (uint32_t)bp * 16 * ROWB + kb);

            uint32_t a[4][4];
            #pragma unroll
            for (int mt = 0; mt < 4; mt++)
                ldsm4(a[mt], uA + a_off + (uint32_t)mt * 16 * ROWB + kb);

            // 16 independent MMAs
            #pragma unroll
            for (int mt = 0; mt < 4; mt++)
                #pragma unroll
                for (int nt = 0; nt < 4; nt++)
                    mma16816(acc[mt][nt], a[mt],
                             bf[nt >> 1][(nt & 1) * 2], bf[nt >> 1][(nt & 1) * 2 + 1]);
        }
    }

    // Epilogue in log2-domain: K = exp2(f2*d - (hi+hj)), clamped arg <= 0,
    // then 4 squarings give the 5-kernel sum. hi/hj register-hoisted.
    const float LG2E = 1.4426950408889634f;
    float cs   = g_scale;
    float clg  = cs * LG2E;
    float f2   = 2.0f * clg;
    int r0 = wy * 64 + (lane >> 2);
    int c0 = wx * 32 + 2 * (lane & 3);

    float hi[8], hj[8];
    #pragma unroll
    for (int mt = 0; mt < 4; mt++) {
        hi[mt * 2]     = clg * sqa[r0 + mt * 16];
        hi[mt * 2 + 1] = clg * sqa[r0 + mt * 16 + 8];
    }
    #pragma unroll
    for (int nt = 0; nt < 4; nt++) {
        hj[nt * 2]     = clg * sqb[c0 + nt * 8];
        hj[nt * 2 + 1] = clg * sqb[c0 + nt * 8 + 1];
    }

    float psum[4] = {0.0f, 0.0f, 0.0f, 0.0f};
    #pragma unroll
    for (int mt = 0; mt < 4; mt++) {
        #pragma unroll
        for (int nt = 0; nt < 4; nt++) {
            #pragma unroll
            for (int e = 0; e < 4; e++) {
                float d   = acc[mt][nt][e];
                float arg = fminf(fmaf(f2, d,
                                  -(hi[mt * 2 + (e >> 1)] + hj[nt * 2 + (e & 1)])),
                                  0.0f);
                float e1  = ex2f(arg);
                float e2  = e1 * e1;
                float e4  = e2 * e2;
                float e8  = e4 * e4;
                float e16 = e8 * e8;
                psum[mt] += ((e1 + e2) + (e4 + e8)) + e16;
            }
        }
    }
    double local = (double)((psum[0] + psum[1]) + (psum[2] + psum[3]));

    // Tile weight: sign from halves, x2 for off-diagonal (mirror tile)
    double w = ((bi < NT / 2) == (bj < NT / 2)) ? 1.0 : -1.0;
    if (bj > bi) w *= 2.0;
    local *= w;

    // Warp shfl reduce (double) + one atomic per warp
    #pragma unroll
    for (int s = 16; s > 0; s >>= 1)
        local += __shfl_xor_sync(0xFFFFFFFFu, local, s);
    if (lane == 0) {
        atomicAdd(&g_result, local);
        __threadfence();
    }

    // Fused finalize: last CTA writes the output
    __syncthreads();
    if (tid == 0) {
        unsigned int old = atomicInc(&g_pair_count, NTRI - 1);
        if (old == NTRI - 1) {
            __threadfence();
            double r = *((volatile double*)&g_result);
            out[0] = (float)(r * (1.0 / ((double)BROWS * (double)BROWS)));
        }
    }
}

// ---------------------------------------------------------------------------
extern "C" void kernel_launch(void* const* d_in, const int* in_sizes, int n_in,
                              void* d_out, int out_size) {
    const float* src = (const float*)d_in[0];
    const float* tgt = (const float*)d_in[1];
    float* out = (float*)d_out;
    (void)in_sizes; (void)n_in; (void)out_size;

    cudaFuncSetAttribute(pair9_kernel,
                         cudaFuncAttributeMaxDynamicSharedMemorySize, DYN_SMEM);

    prep_kernel<<<PREPB, 256>>>(src, tgt);
    pair9_kernel<<<NTRI, 256, DYN_SMEM>>>(out);
}